// round 1
// baseline (speedup 1.0000x reference)
#include <cuda_runtime.h>
#include <math.h>
#include <stdint.h>

#define D_     1024
#define H_     16
#define HD_    64
#define FF_    4096
#define B_     2
#define S_     2048
#define T_     (B_*S_)     // 4096 tokens
#define EPS_   1e-5f

// ---------------- scratch (device globals; allocation-free) ----------------
__device__ float g_h  [T_ * D_];        // LN1 out
__device__ float g_qkv[T_ * 3 * D_];    // qkv
__device__ float g_ctx[T_ * D_];        // attention context
__device__ float g_x1 [T_ * D_];        // x + attn proj
__device__ float g_h2 [T_ * D_];        // LN2 out
__device__ float g_m  [T_ * FF_];       // MLP hidden

// ---------------- LayerNorm (torch-faithful: ddof=1, eps added to std) -----
__global__ __launch_bounds__(256) void ln_kernel(
    const float* __restrict__ x, const float* __restrict__ scale,
    const float* __restrict__ shift, float* __restrict__ out)
{
    const int row = blockIdx.x;
    const int tid = threadIdx.x;
    const float4 v = ((const float4*)(x + (size_t)row * D_))[tid];

    float s  = v.x + v.y + v.z + v.w;
    float ss = v.x*v.x + v.y*v.y + v.z*v.z + v.w*v.w;
    #pragma unroll
    for (int o = 16; o > 0; o >>= 1) {
        s  += __shfl_xor_sync(0xffffffffu, s,  o);
        ss += __shfl_xor_sync(0xffffffffu, ss, o);
    }
    __shared__ float sm[8], sm2[8];
    const int w = tid >> 5, l = tid & 31;
    if (l == 0) { sm[w] = s; sm2[w] = ss; }
    __syncthreads();
    float ts = 0.f, tss = 0.f;
    #pragma unroll
    for (int i = 0; i < 8; i++) { ts += sm[i]; tss += sm2[i]; }

    const float mean = ts * (1.0f / D_);
    const float var  = (tss - (float)D_ * mean * mean) * (1.0f / (D_ - 1));
    const float inv  = 1.0f / (sqrtf(var) + EPS_);

    const float4 sc = ((const float4*)scale)[tid];
    const float4 sh = ((const float4*)shift)[tid];
    float4 o;
    o.x = sh.x + sc.x * (v.x - mean) * inv;
    o.y = sh.y + sc.y * (v.y - mean) * inv;
    o.z = sh.z + sc.z * (v.z - mean) * inv;
    o.w = sh.w + sc.w * (v.w - mean) * inv;
    ((float4*)(out + (size_t)row * D_))[tid] = o;
}

// ---------------- GELU (tanh approx, matches reference) --------------------
__device__ __forceinline__ float gelu_f(float x) {
    const float c = 0.7978845608028654f;
    float x3 = x * x * x;
    return 0.5f * x * (1.0f + tanhf(c * (x + 0.044715f * x3)));
}

// ---------------- NT SGEMM: C[M,N] = A[M,K] . B[N,K]^T (+bias,+gelu,+res) --
// BM=BN=128, BK=16, 256 threads, 8x8 per-thread tile.
#define GBM 128
#define GBN 128
#define GBK 16

template<bool BIAS, bool GELU_ACT, bool RES>
__global__ __launch_bounds__(256) void gemm_nt(
    const float* __restrict__ A, const float* __restrict__ B,
    const float* __restrict__ bias, const float* __restrict__ res,
    float* __restrict__ C, int M, int N, int K)
{
    __shared__ float As[GBK][GBM + 4];
    __shared__ float Bs[GBK][GBN + 4];

    const int tid = threadIdx.x;
    const int tx = tid & 15;         // 0..15 -> N
    const int ty = tid >> 4;         // 0..15 -> M
    const float* Ab = A + (size_t)blockIdx.y * GBM * K;
    const float* Bb = B + (size_t)blockIdx.x * GBN * K;

    float acc[8][8];
    #pragma unroll
    for (int i = 0; i < 8; i++)
        #pragma unroll
        for (int j = 0; j < 8; j++) acc[i][j] = 0.f;

    const int lr = tid >> 2;            // 0..63
    const int lc = (tid & 3) << 2;      // 0,4,8,12

    for (int k0 = 0; k0 < K; k0 += GBK) {
        #pragma unroll
        for (int rr = 0; rr < 2; rr++) {
            const int r = lr + rr * 64;
            float4 va = *(const float4*)(Ab + (size_t)r * K + k0 + lc);
            As[lc+0][r] = va.x; As[lc+1][r] = va.y;
            As[lc+2][r] = va.z; As[lc+3][r] = va.w;
            float4 vb = *(const float4*)(Bb + (size_t)r * K + k0 + lc);
            Bs[lc+0][r] = vb.x; Bs[lc+1][r] = vb.y;
            Bs[lc+2][r] = vb.z; Bs[lc+3][r] = vb.w;
        }
        __syncthreads();
        #pragma unroll
        for (int k = 0; k < GBK; k++) {
            float a[8], b[8];
            #pragma unroll
            for (int i = 0; i < 8; i++) a[i] = As[k][ty * 8 + i];
            #pragma unroll
            for (int j = 0; j < 8; j++) b[j] = Bs[k][tx * 8 + j];
            #pragma unroll
            for (int i = 0; i < 8; i++)
                #pragma unroll
                for (int j = 0; j < 8; j++)
                    acc[i][j] += a[i] * b[j];
        }
        __syncthreads();
    }

    // epilogue
    #pragma unroll
    for (int i = 0; i < 8; i++) {
        const int row = blockIdx.y * GBM + ty * 8 + i;
        const size_t rbase = (size_t)row * N;
        #pragma unroll
        for (int j = 0; j < 8; j++) {
            const int col = blockIdx.x * GBN + tx * 8 + j;
            float v = acc[i][j];
            if (BIAS)     v += bias[col];
            if (GELU_ACT) v  = gelu_f(v);
            if (RES)      v += res[rbase + col];
            C[rbase + col] = v;
        }
    }
}

// ---------------- Causal flash attention (fp32, HD=64) ---------------------
// Grid: (S/QT, B*H). 128 threads; thread t owns query row qt*128+t.
// q in smem (padded stride 68), K/V tiles of 32 keys in smem, scores s[32]
// and accumulator o[64] in registers, online softmax.
#define QT_ 128
#define KT_ 32
#define QPAD 68

__global__ __launch_bounds__(128) void attn_kernel(
    const float* __restrict__ qkv, float* __restrict__ ctx)
{
    extern __shared__ float smem[];
    float* qs = smem;                       // [128][68]
    float* ks = qs + QT_ * QPAD;            // [32][64]
    float* vs = ks + KT_ * HD_;             // [32][64]

    const int qt  = blockIdx.x;
    const int bh  = blockIdx.y;
    const int b   = bh / H_;
    const int h   = bh % H_;
    const int tid = threadIdx.x;
    const int tok0 = b * S_ + qt * QT_;

    // cooperative Q load (pre-scaled by 1/sqrt(HD)=0.125)
    for (int i = tid; i < QT_ * 16; i += 128) {
        const int r = i >> 4, c = i & 15;
        float4 v = *((const float4*)(qkv + (size_t)(tok0 + r) * (3 * D_) + h * HD_) + c);
        float* dst = qs + r * QPAD + c * 4;
        dst[0] = v.x * 0.125f; dst[1] = v.y * 0.125f;
        dst[2] = v.z * 0.125f; dst[3] = v.w * 0.125f;
    }

    float m = -INFINITY, lsum = 0.f;
    float o[HD_];
    #pragma unroll
    for (int d = 0; d < HD_; d++) o[d] = 0.f;

    const int qidx = qt * QT_ + tid;
    const int nk = qt * 4 + 4;   // ktiles covering keys 0..qt*128+127

    for (int j = 0; j < nk; j++) {
        __syncthreads();
        // load K,V tile (32x64 each)
        for (int i = tid; i < KT_ * 16; i += 128) {
            const int r = i >> 4, c = i & 15;
            const size_t base = (size_t)(b * S_ + j * KT_ + r) * (3 * D_) + h * HD_;
            ((float4*)(ks + r * HD_))[c] = *((const float4*)(qkv + base + D_) + c);
            ((float4*)(vs + r * HD_))[c] = *((const float4*)(qkv + base + 2 * D_) + c);
        }
        __syncthreads();

        float s[KT_];
        #pragma unroll
        for (int kk = 0; kk < KT_; kk++) s[kk] = 0.f;

        for (int d0 = 0; d0 < HD_; d0 += 4) {
            const float4 q4 = *(const float4*)(qs + tid * QPAD + d0);
            #pragma unroll
            for (int kk = 0; kk < KT_; kk++) {
                const float4 k4 = *(const float4*)(ks + kk * HD_ + d0);
                s[kk] += q4.x * k4.x + q4.y * k4.y + q4.z * k4.z + q4.w * k4.w;
            }
        }

        // causal mask + running max
        float smax = -INFINITY;
        const int kbase = j * KT_;
        #pragma unroll
        for (int kk = 0; kk < KT_; kk++) {
            if (kbase + kk > qidx) s[kk] = -INFINITY;
            smax = fmaxf(smax, s[kk]);
        }
        const float mnew = fmaxf(m, smax);
        const float corr = __expf(m - mnew);
        float psum = 0.f;
        #pragma unroll
        for (int kk = 0; kk < KT_; kk++) {
            float p = __expf(s[kk] - mnew);
            s[kk] = p;
            psum += p;
        }
        m = mnew;
        lsum = lsum * corr + psum;
        #pragma unroll
        for (int d = 0; d < HD_; d++) o[d] *= corr;

        #pragma unroll
        for (int kk = 0; kk < KT_; kk++) {
            const float p = s[kk];
            #pragma unroll
            for (int dd = 0; dd < 16; dd++) {
                const float4 v4 = *(const float4*)(vs + kk * HD_ + dd * 4);
                o[dd*4+0] += p * v4.x;
                o[dd*4+1] += p * v4.y;
                o[dd*4+2] += p * v4.z;
                o[dd*4+3] += p * v4.w;
            }
        }
    }

    const float invl = 1.0f / lsum;
    float* op = ctx + (size_t)(tok0 + tid) * D_ + h * HD_;
    #pragma unroll
    for (int dd = 0; dd < 16; dd++) {
        float4 r;
        r.x = o[dd*4+0] * invl; r.y = o[dd*4+1] * invl;
        r.z = o[dd*4+2] * invl; r.w = o[dd*4+3] * invl;
        ((float4*)op)[dd] = r;
    }
}

// ---------------- launch ---------------------------------------------------
extern "C" void kernel_launch(void* const* d_in, const int* in_sizes, int n_in,
                              void* d_out, int out_size)
{
    const float* x      = (const float*)d_in[0];
    const float* scale1 = (const float*)d_in[1];
    const float* shift1 = (const float*)d_in[2];
    const float* Wqkv   = (const float*)d_in[3];
    const float* Wo_w   = (const float*)d_in[4];
    const float* Wo_b   = (const float*)d_in[5];
    const float* scale2 = (const float*)d_in[6];
    const float* shift2 = (const float*)d_in[7];
    const float* W1     = (const float*)d_in[8];
    const float* b1     = (const float*)d_in[9];
    const float* W2     = (const float*)d_in[10];
    const float* b2     = (const float*)d_in[11];
    float* out = (float*)d_out;

    float *h, *qkv, *ctx, *x1, *h2, *mbuf;
    cudaGetSymbolAddress((void**)&h,    g_h);
    cudaGetSymbolAddress((void**)&qkv,  g_qkv);
    cudaGetSymbolAddress((void**)&ctx,  g_ctx);
    cudaGetSymbolAddress((void**)&x1,   g_x1);
    cudaGetSymbolAddress((void**)&h2,   g_h2);
    cudaGetSymbolAddress((void**)&mbuf, g_m);

    const int attn_smem = (QT_ * QPAD + 2 * KT_ * HD_) * (int)sizeof(float); // 51200
    cudaFuncSetAttribute(attn_kernel, cudaFuncAttributeMaxDynamicSharedMemorySize, attn_smem);

    // 1. LN1
    ln_kernel<<<T_, 256>>>(x, scale1, shift1, h);
    // 2. QKV = h @ Wqkv^T   [4096,3072,1024]
    gemm_nt<false,false,false><<<dim3(3 * D_ / GBN, T_ / GBM), 256>>>(
        h, Wqkv, nullptr, nullptr, qkv, T_, 3 * D_, D_);
    // 3. causal attention
    attn_kernel<<<dim3(S_ / QT_, B_ * H_), 128, attn_smem>>>(qkv, ctx);
    // 4. x1 = x + ctx @ Wo^T + Wo_b   [4096,1024,1024]
    gemm_nt<true,false,true><<<dim3(D_ / GBN, T_ / GBM), 256>>>(
        ctx, Wo_w, Wo_b, x, x1, T_, D_, D_);
    // 5. LN2
    ln_kernel<<<T_, 256>>>(x1, scale2, shift2, h2);
    // 6. m = gelu(h2 @ W1^T + b1)   [4096,4096,1024]
    gemm_nt<true,true,false><<<dim3(FF_ / GBN, T_ / GBM), 256>>>(
        h2, W1, b1, nullptr, mbuf, T_, FF_, D_);
    // 7. out = x1 + m @ W2^T + b2   [4096,1024,4096]
    gemm_nt<true,false,true><<<dim3(D_ / GBN, T_ / GBM), 256>>>(
        mbuf, W2, b2, x1, out, T_, D_, FF_);
}

// round 3
// speedup vs baseline: 1.9379x; 1.9379x over previous
#include <cuda_runtime.h>
#include <math.h>
#include <stdint.h>

#define D_     1024
#define H_     16
#define HD_    64
#define FF_    4096
#define B_     2
#define S_     2048
#define T_     (B_*S_)     // 4096 tokens
#define EPS_   1e-5f

// ---------------- scratch (device globals; allocation-free) ----------------
__device__ float g_h  [T_ * D_];        // LN1 out (tf32-rounded)
__device__ float g_qkv[T_ * 3 * D_];    // qkv
__device__ float g_ctx[T_ * D_];        // attention context (tf32-rounded)
__device__ float g_x1 [T_ * D_];        // x + attn proj (exact)
__device__ float g_h2 [T_ * D_];        // LN2 out (tf32-rounded)
__device__ float g_m  [T_ * FF_];       // MLP hidden (tf32-rounded)
// tf32-rounded weights
__device__ float g_wqkv[3 * D_ * D_];
__device__ float g_wo  [D_ * D_];
__device__ float g_w1  [FF_ * D_];
__device__ float g_w2  [D_ * FF_];

// ---------------- small helpers -------------------------------------------
__device__ __forceinline__ uint32_t smem_u32(const void* p) {
    uint32_t a;
    asm("{ .reg .u64 t; cvta.to.shared.u64 t, %1; cvt.u32.u64 %0, t; }" : "=r"(a) : "l"(p));
    return a;
}
__device__ __forceinline__ float tf32r(float x) {
    uint32_t u;
    asm("cvt.rna.tf32.f32 %0, %1;" : "=r"(u) : "f"(x));
    return __uint_as_float(u);
}
__device__ __forceinline__ float gelu_f(float x) {
    const float c = 0.7978845608028654f;
    float x3 = x * x * x;
    return 0.5f * x * (1.0f + tanhf(c * (x + 0.044715f * x3)));
}
__device__ __forceinline__ void cp16(uint32_t dst, const void* src) {
    asm volatile("cp.async.cg.shared.global [%0], [%1], 16;" :: "r"(dst), "l"(src) : "memory");
}
__device__ __forceinline__ void mma_tf32(float& c0, float& c1, float& c2, float& c3,
                                         uint32_t a0, uint32_t a1, uint32_t a2, uint32_t a3,
                                         uint32_t b0, uint32_t b1) {
    asm volatile(
        "mma.sync.aligned.m16n8k8.row.col.f32.tf32.tf32.f32 "
        "{%0,%1,%2,%3}, {%4,%5,%6,%7}, {%8,%9}, {%0,%1,%2,%3};"
        : "+f"(c0), "+f"(c1), "+f"(c2), "+f"(c3)
        : "r"(a0), "r"(a1), "r"(a2), "r"(a3), "r"(b0), "r"(b1));
}

// ---------------- tf32 rounding pass for weights ---------------------------
__global__ __launch_bounds__(256) void round_w_kernel(const float* __restrict__ in,
                                                      float* __restrict__ out, int n4) {
    int i = blockIdx.x * 256 + threadIdx.x;
    if (i < n4) {
        float4 v = ((const float4*)in)[i];
        v.x = tf32r(v.x); v.y = tf32r(v.y); v.z = tf32r(v.z); v.w = tf32r(v.w);
        ((float4*)out)[i] = v;
    }
}

// ---------------- LayerNorm (ddof=1, eps added to std), tf32-rounded out ---
__global__ __launch_bounds__(256) void ln_kernel(
    const float* __restrict__ x, const float* __restrict__ scale,
    const float* __restrict__ shift, float* __restrict__ out)
{
    const int row = blockIdx.x;
    const int tid = threadIdx.x;
    const float4 v = ((const float4*)(x + (size_t)row * D_))[tid];

    float s  = v.x + v.y + v.z + v.w;
    float ss = v.x*v.x + v.y*v.y + v.z*v.z + v.w*v.w;
    #pragma unroll
    for (int o = 16; o > 0; o >>= 1) {
        s  += __shfl_xor_sync(0xffffffffu, s,  o);
        ss += __shfl_xor_sync(0xffffffffu, ss, o);
    }
    __shared__ float sm[8], sm2[8];
    const int w = tid >> 5, l = tid & 31;
    if (l == 0) { sm[w] = s; sm2[w] = ss; }
    __syncthreads();
    float ts = 0.f, tss = 0.f;
    #pragma unroll
    for (int i = 0; i < 8; i++) { ts += sm[i]; tss += sm2[i]; }

    const float mean = ts * (1.0f / D_);
    const float var  = (tss - (float)D_ * mean * mean) * (1.0f / (D_ - 1));
    const float inv  = 1.0f / (sqrtf(var) + EPS_);

    const float4 sc = ((const float4*)scale)[tid];
    const float4 sh = ((const float4*)shift)[tid];
    float4 o;
    o.x = tf32r(sh.x + sc.x * (v.x - mean) * inv);
    o.y = tf32r(sh.y + sc.y * (v.y - mean) * inv);
    o.z = tf32r(sh.z + sc.z * (v.z - mean) * inv);
    o.w = tf32r(sh.w + sc.w * (v.w - mean) * inv);
    ((float4*)(out + (size_t)row * D_))[tid] = o;
}

// ---------------- TF32 mma.sync NT GEMM: C[M,N] = A[M,K] . B[N,K]^T --------
// CTA 128x128, BK=32, 256 threads (8 warps, 2x4), warp tile 64x32,
// 3-stage cp.async pipeline, padded smem (stride 36 floats, conflict-free).
#define BM 128
#define BN 128
#define BK 32
#define PADS 36                       // floats per smem row (32 + 4 pad)
#define STAGEF (BM*PADS + BN*PADS)    // 9216 floats / stage
#define NSTAGE 3
#define GEMM_SMEM (NSTAGE*STAGEF*4)   // 110592 B

__device__ __forceinline__ void stage_load(uint32_t smbase, int s,
                                           const float* __restrict__ Ab,
                                           const float* __restrict__ Bb,
                                           int K, int k0, int tid) {
    const uint32_t abase = smbase + (uint32_t)s * STAGEF * 4;
    const uint32_t bbase = abase + BM * PADS * 4;
    #pragma unroll
    for (int i = 0; i < 4; i++) {
        int idx = i * 256 + tid;           // 1024 granules of 16B
        int r = idx >> 3, g = idx & 7;
        cp16(abase + (r * PADS + g * 4) * 4, Ab + (size_t)r * K + k0 + g * 4);
        cp16(bbase + (r * PADS + g * 4) * 4, Bb + (size_t)r * K + k0 + g * 4);
    }
}

template<bool BIAS, bool GELU_ACT, bool RES, bool ROUND>
__global__ __launch_bounds__(256, 1) void gemm_mma(
    const float* __restrict__ A, const float* __restrict__ B,
    const float* __restrict__ bias, const float* __restrict__ res,
    float* __restrict__ C, int M, int N, int K)
{
    extern __shared__ float smf[];
    const uint32_t smbase = smem_u32(smf);
    const int tid  = threadIdx.x;
    const int wid  = tid >> 5, lane = tid & 31;
    const int wm   = wid >> 2, wn = wid & 3;       // 2 x 4 warp grid
    const int g    = lane >> 2, t = lane & 3;

    const float* Ab = A + (size_t)blockIdx.y * BM * K;
    const float* Bb = B + (size_t)blockIdx.x * BN * K;

    float acc[4][4][4];
    #pragma unroll
    for (int i = 0; i < 4; i++)
        #pragma unroll
        for (int j = 0; j < 4; j++)
            #pragma unroll
            for (int q = 0; q < 4; q++) acc[i][j][q] = 0.f;

    const int nch = K >> 5;

    stage_load(smbase, 0, Ab, Bb, K, 0, tid);
    asm volatile("cp.async.commit_group;" ::: "memory");
    stage_load(smbase, 1, Ab, Bb, K, BK, tid);
    asm volatile("cp.async.commit_group;" ::: "memory");

    for (int i = 0; i < nch; i++) {
        const int s = i % NSTAGE;
        if (i + 2 < nch) {
            asm volatile("cp.async.wait_group 1;" ::: "memory");
        } else {
            asm volatile("cp.async.wait_group 0;" ::: "memory");
        }
        __syncthreads();
        if (i + 2 < nch) {
            stage_load(smbase, (i + 2) % NSTAGE, Ab, Bb, K, (i + 2) * BK, tid);
            asm volatile("cp.async.commit_group;" ::: "memory");
        }

        const float* as = smf + (size_t)s * STAGEF;
        const float* bs = as + BM * PADS;

        #pragma unroll
        for (int ks = 0; ks < 4; ks++) {
            const int k0 = ks * 8;
            uint32_t af[4][4], bf[4][2];
            #pragma unroll
            for (int mt = 0; mt < 4; mt++) {
                const int row = wm * 64 + mt * 16;
                af[mt][0] = __float_as_uint(as[(row + g)     * PADS + k0 + t]);
                af[mt][1] = __float_as_uint(as[(row + g + 8) * PADS + k0 + t]);
                af[mt][2] = __float_as_uint(as[(row + g)     * PADS + k0 + t + 4]);
                af[mt][3] = __float_as_uint(as[(row + g + 8) * PADS + k0 + t + 4]);
            }
            #pragma unroll
            for (int nt = 0; nt < 4; nt++) {
                const int col = wn * 32 + nt * 8 + g;
                bf[nt][0] = __float_as_uint(bs[col * PADS + k0 + t]);
                bf[nt][1] = __float_as_uint(bs[col * PADS + k0 + t + 4]);
            }
            #pragma unroll
            for (int mt = 0; mt < 4; mt++)
                #pragma unroll
                for (int nt = 0; nt < 4; nt++)
                    mma_tf32(acc[mt][nt][0], acc[mt][nt][1], acc[mt][nt][2], acc[mt][nt][3],
                             af[mt][0], af[mt][1], af[mt][2], af[mt][3],
                             bf[nt][0], bf[nt][1]);
        }
        __syncthreads();
    }

    // ------------- epilogue -------------
    #pragma unroll
    for (int mt = 0; mt < 4; mt++) {
        const int r0 = blockIdx.y * BM + wm * 64 + mt * 16 + g;
        #pragma unroll
        for (int nt = 0; nt < 4; nt++) {
            const int c0 = blockIdx.x * BN + wn * 32 + nt * 8 + 2 * t;
            float b0 = 0.f, b1 = 0.f;
            if (BIAS) { b0 = bias[c0]; b1 = bias[c0 + 1]; }
            float v00 = acc[mt][nt][0] + b0, v01 = acc[mt][nt][1] + b1;
            float v10 = acc[mt][nt][2] + b0, v11 = acc[mt][nt][3] + b1;
            if (GELU_ACT) { v00 = gelu_f(v00); v01 = gelu_f(v01);
                            v10 = gelu_f(v10); v11 = gelu_f(v11); }
            if (RES) {
                const float2 r0v = *(const float2*)(res + (size_t)r0 * N + c0);
                const float2 r1v = *(const float2*)(res + (size_t)(r0 + 8) * N + c0);
                v00 += r0v.x; v01 += r0v.y; v10 += r1v.x; v11 += r1v.y;
            }
            if (ROUND) { v00 = tf32r(v00); v01 = tf32r(v01);
                         v10 = tf32r(v10); v11 = tf32r(v11); }
            *(float2*)(C + (size_t)r0 * N + c0)       = make_float2(v00, v01);
            *(float2*)(C + (size_t)(r0 + 8) * N + c0) = make_float2(v10, v11);
        }
    }
}

// ---------------- Causal flash attention (fp32, HD=64) ---------------------
#define QT_ 128
#define KT_ 32
#define QPAD 68

__global__ __launch_bounds__(128) void attn_kernel(
    const float* __restrict__ qkv, float* __restrict__ ctx)
{
    extern __shared__ float smem[];
    float* qs = smem;                       // [128][68]
    float* ks = qs + QT_ * QPAD;            // [32][64]
    float* vs = ks + KT_ * HD_;             // [32][64]

    const int qt  = blockIdx.x;
    const int bh  = blockIdx.y;
    const int b   = bh / H_;
    const int h   = bh % H_;
    const int tid = threadIdx.x;
    const int tok0 = b * S_ + qt * QT_;

    for (int i = tid; i < QT_ * 16; i += 128) {
        const int r = i >> 4, c = i & 15;
        float4 v = *((const float4*)(qkv + (size_t)(tok0 + r) * (3 * D_) + h * HD_) + c);
        float* dst = qs + r * QPAD + c * 4;
        dst[0] = v.x * 0.125f; dst[1] = v.y * 0.125f;
        dst[2] = v.z * 0.125f; dst[3] = v.w * 0.125f;
    }

    float m = -INFINITY, lsum = 0.f;
    float o[HD_];
    #pragma unroll
    for (int d = 0; d < HD_; d++) o[d] = 0.f;

    const int qidx = qt * QT_ + tid;
    const int nk = qt * 4 + 4;

    for (int j = 0; j < nk; j++) {
        __syncthreads();
        for (int i = tid; i < KT_ * 16; i += 128) {
            const int r = i >> 4, c = i & 15;
            const size_t base = (size_t)(b * S_ + j * KT_ + r) * (3 * D_) + h * HD_;
            ((float4*)(ks + r * HD_))[c] = *((const float4*)(qkv + base + D_) + c);
            ((float4*)(vs + r * HD_))[c] = *((const float4*)(qkv + base + 2 * D_) + c);
        }
        __syncthreads();

        float s[KT_];
        #pragma unroll
        for (int kk = 0; kk < KT_; kk++) s[kk] = 0.f;

        for (int d0 = 0; d0 < HD_; d0 += 4) {
            const float4 q4 = *(const float4*)(qs + tid * QPAD + d0);
            #pragma unroll
            for (int kk = 0; kk < KT_; kk++) {
                const float4 k4 = *(const float4*)(ks + kk * HD_ + d0);
                s[kk] += q4.x * k4.x + q4.y * k4.y + q4.z * k4.z + q4.w * k4.w;
            }
        }

        float smax = -INFINITY;
        const int kbase = j * KT_;
        #pragma unroll
        for (int kk = 0; kk < KT_; kk++) {
            if (kbase + kk > qidx) s[kk] = -INFINITY;
            smax = fmaxf(smax, s[kk]);
        }
        const float mnew = fmaxf(m, smax);
        const float corr = __expf(m - mnew);
        float psum = 0.f;
        #pragma unroll
        for (int kk = 0; kk < KT_; kk++) {
            float p = __expf(s[kk] - mnew);
            s[kk] = p;
            psum += p;
        }
        m = mnew;
        lsum = lsum * corr + psum;
        #pragma unroll
        for (int d = 0; d < HD_; d++) o[d] *= corr;

        #pragma unroll
        for (int kk = 0; kk < KT_; kk++) {
            const float p = s[kk];
            #pragma unroll
            for (int dd = 0; dd < 16; dd++) {
                const float4 v4 = *(const float4*)(vs + kk * HD_ + dd * 4);
                o[dd*4+0] += p * v4.x;
                o[dd*4+1] += p * v4.y;
                o[dd*4+2] += p * v4.z;
                o[dd*4+3] += p * v4.w;
            }
        }
    }

    const float invl = 1.0f / lsum;
    float* op = ctx + (size_t)(tok0 + tid) * D_ + h * HD_;
    #pragma unroll
    for (int dd = 0; dd < 16; dd++) {
        float4 r;
        r.x = tf32r(o[dd*4+0] * invl); r.y = tf32r(o[dd*4+1] * invl);
        r.z = tf32r(o[dd*4+2] * invl); r.w = tf32r(o[dd*4+3] * invl);
        ((float4*)op)[dd] = r;
    }
}

// ---------------- launch ---------------------------------------------------
extern "C" void kernel_launch(void* const* d_in, const int* in_sizes, int n_in,
                              void* d_out, int out_size)
{
    const float* x      = (const float*)d_in[0];
    const float* scale1 = (const float*)d_in[1];
    const float* shift1 = (const float*)d_in[2];
    const float* Wqkv   = (const float*)d_in[3];
    const float* Wo_w   = (const float*)d_in[4];
    const float* Wo_b   = (const float*)d_in[5];
    const float* scale2 = (const float*)d_in[6];
    const float* shift2 = (const float*)d_in[7];
    const float* W1     = (const float*)d_in[8];
    const float* b1     = (const float*)d_in[9];
    const float* W2     = (const float*)d_in[10];
    const float* b2     = (const float*)d_in[11];
    float* out = (float*)d_out;

    float *h, *qkv, *ctx, *x1, *h2, *mbuf, *wqkv, *wo, *w1, *w2;
    cudaGetSymbolAddress((void**)&h,    g_h);
    cudaGetSymbolAddress((void**)&qkv,  g_qkv);
    cudaGetSymbolAddress((void**)&ctx,  g_ctx);
    cudaGetSymbolAddress((void**)&x1,   g_x1);
    cudaGetSymbolAddress((void**)&h2,   g_h2);
    cudaGetSymbolAddress((void**)&mbuf, g_m);
    cudaGetSymbolAddress((void**)&wqkv, g_wqkv);
    cudaGetSymbolAddress((void**)&wo,   g_wo);
    cudaGetSymbolAddress((void**)&w1,   g_w1);
    cudaGetSymbolAddress((void**)&w2,   g_w2);

    const int attn_smem = (QT_ * QPAD + 2 * KT_ * HD_) * (int)sizeof(float);
    cudaFuncSetAttribute(attn_kernel, cudaFuncAttributeMaxDynamicSharedMemorySize, attn_smem);
    cudaFuncSetAttribute(gemm_mma<false,false,false,false>, cudaFuncAttributeMaxDynamicSharedMemorySize, GEMM_SMEM);
    cudaFuncSetAttribute(gemm_mma<true,false,true,false>,   cudaFuncAttributeMaxDynamicSharedMemorySize, GEMM_SMEM);
    cudaFuncSetAttribute(gemm_mma<true,true,false,true>,    cudaFuncAttributeMaxDynamicSharedMemorySize, GEMM_SMEM);

    // 0. round weights to tf32 (RNA) into scratch
    round_w_kernel<<<(3*D_*D_/4 + 255)/256, 256>>>(Wqkv, wqkv, 3*D_*D_/4);
    round_w_kernel<<<(D_*D_/4   + 255)/256, 256>>>(Wo_w, wo,   D_*D_/4);
    round_w_kernel<<<(FF_*D_/4  + 255)/256, 256>>>(W1,   w1,   FF_*D_/4);
    round_w_kernel<<<(D_*FF_/4  + 255)/256, 256>>>(W2,   w2,   D_*FF_/4);

    // 1. LN1 (tf32-rounded output)
    ln_kernel<<<T_, 256>>>(x, scale1, shift1, h);
    // 2. QKV = h @ Wqkv^T   [4096,3072,1024]
    gemm_mma<false,false,false,false><<<dim3(3*D_/BN, T_/BM), 256, GEMM_SMEM>>>(
        h, wqkv, nullptr, nullptr, qkv, T_, 3*D_, D_);
    // 3. causal attention (ctx tf32-rounded)
    attn_kernel<<<dim3(S_/QT_, B_*H_), 128, attn_smem>>>(qkv, ctx);
    // 4. x1 = x + ctx @ Wo^T + Wo_b   [4096,1024,1024]
    gemm_mma<true,false,true,false><<<dim3(D_/BN, T_/BM), 256, GEMM_SMEM>>>(
        ctx, wo, Wo_b, x, x1, T_, D_, D_);
    // 5. LN2 (tf32-rounded output)
    ln_kernel<<<T_, 256>>>(x1, scale2, shift2, h2);
    // 6. m = gelu(h2 @ W1^T + b1), tf32-rounded   [4096,4096,1024]
    gemm_mma<true,true,false,true><<<dim3(FF_/BN, T_/BM), 256, GEMM_SMEM>>>(
        h2, w1, b1, nullptr, mbuf, T_, FF_, D_);
    // 7. out = x1 + m @ W2^T + b2   [4096,1024,4096]
    gemm_mma<true,false,true,false><<<dim3(D_/BN, T_/BM), 256, GEMM_SMEM>>>(
        mbuf, w2, b2, x1, out, T_, D_, FF_);
}

// round 4
// speedup vs baseline: 3.0783x; 1.5885x over previous
#include <cuda_runtime.h>
#include <math.h>
#include <stdint.h>

#define D_     1024
#define H_     16
#define HD_    64
#define FF_    4096
#define B_     2
#define S_     2048
#define T_     (B_*S_)     // 4096 tokens
#define EPS_   1e-5f

// ---------------- scratch (device globals; allocation-free) ----------------
__device__ float g_h  [T_ * D_];        // LN1 out (tf32-rounded)
__device__ float g_qkv[T_ * 3 * D_];    // qkv (tf32-rounded)
__device__ float g_ctx[T_ * D_];        // attention context (tf32-rounded)
__device__ float g_x1 [T_ * D_];        // x + attn proj (exact)
__device__ float g_h2 [T_ * D_];        // LN2 out (tf32-rounded)
__device__ float g_m  [T_ * FF_];       // MLP hidden (tf32-rounded)
// tf32-rounded weights
__device__ float g_wqkv[3 * D_ * D_];
__device__ float g_wo  [D_ * D_];
__device__ float g_w1  [FF_ * D_];
__device__ float g_w2  [D_ * FF_];

// ---------------- small helpers -------------------------------------------
__device__ __forceinline__ uint32_t smem_u32(const void* p) {
    uint32_t a;
    asm("{ .reg .u64 t; cvta.to.shared.u64 t, %1; cvt.u32.u64 %0, t; }" : "=r"(a) : "l"(p));
    return a;
}
__device__ __forceinline__ float tf32r(float x) {
    uint32_t u;
    asm("cvt.rna.tf32.f32 %0, %1;" : "=r"(u) : "f"(x));
    return __uint_as_float(u);
}
__device__ __forceinline__ float gelu_f(float x) {
    const float c = 0.7978845608028654f;
    float x3 = x * x * x;
    return 0.5f * x * (1.0f + tanhf(c * (x + 0.044715f * x3)));
}
__device__ __forceinline__ void cp16(uint32_t dst, const void* src) {
    asm volatile("cp.async.cg.shared.global [%0], [%1], 16;" :: "r"(dst), "l"(src) : "memory");
}
__device__ __forceinline__ void mma_tf32(float& c0, float& c1, float& c2, float& c3,
                                         uint32_t a0, uint32_t a1, uint32_t a2, uint32_t a3,
                                         uint32_t b0, uint32_t b1) {
    asm volatile(
        "mma.sync.aligned.m16n8k8.row.col.f32.tf32.tf32.f32 "
        "{%0,%1,%2,%3}, {%4,%5,%6,%7}, {%8,%9}, {%0,%1,%2,%3};"
        : "+f"(c0), "+f"(c1), "+f"(c2), "+f"(c3)
        : "r"(a0), "r"(a1), "r"(a2), "r"(a3), "r"(b0), "r"(b1));
}
// fast exp on the FMA pipe (no MUFU): ~1e-6 rel err over useful range
__device__ __forceinline__ float fexp(float x) {
    float y = fmaxf(x * 1.4426950408889634f, -126.0f);
    float z = y + 12582912.0f;                 // magic round-to-nearest
    float n = z - 12582912.0f;
    float f = y - n;                            // [-0.5, 0.5]
    float q = f * 0.6931471805599453f;
    float p = 0.008333345f;
    p = p * q + 0.041666667f;
    p = p * q + 0.166666667f;
    p = p * q + 0.5f;
    p = p * q + 1.0f;
    p = p * q + 1.0f;
    int e = (int)n;
    return __int_as_float(__float_as_int(p) + (e << 23));
}

// ---------------- tf32 rounding pass for weights ---------------------------
__global__ __launch_bounds__(256) void round_w_kernel(const float* __restrict__ in,
                                                      float* __restrict__ out, int n4) {
    int i = blockIdx.x * 256 + threadIdx.x;
    if (i < n4) {
        float4 v = ((const float4*)in)[i];
        v.x = tf32r(v.x); v.y = tf32r(v.y); v.z = tf32r(v.z); v.w = tf32r(v.w);
        ((float4*)out)[i] = v;
    }
}

// ---------------- LayerNorm (ddof=1, eps added to std), tf32-rounded out ---
__global__ __launch_bounds__(256) void ln_kernel(
    const float* __restrict__ x, const float* __restrict__ scale,
    const float* __restrict__ shift, float* __restrict__ out)
{
    const int row = blockIdx.x;
    const int tid = threadIdx.x;
    const float4 v = ((const float4*)(x + (size_t)row * D_))[tid];

    float s  = v.x + v.y + v.z + v.w;
    float ss = v.x*v.x + v.y*v.y + v.z*v.z + v.w*v.w;
    #pragma unroll
    for (int o = 16; o > 0; o >>= 1) {
        s  += __shfl_xor_sync(0xffffffffu, s,  o);
        ss += __shfl_xor_sync(0xffffffffu, ss, o);
    }
    __shared__ float sm[8], sm2[8];
    const int w = tid >> 5, l = tid & 31;
    if (l == 0) { sm[w] = s; sm2[w] = ss; }
    __syncthreads();
    float ts = 0.f, tss = 0.f;
    #pragma unroll
    for (int i = 0; i < 8; i++) { ts += sm[i]; tss += sm2[i]; }

    const float mean = ts * (1.0f / D_);
    const float var  = (tss - (float)D_ * mean * mean) * (1.0f / (D_ - 1));
    const float inv  = 1.0f / (sqrtf(var) + EPS_);

    const float4 sc = ((const float4*)scale)[tid];
    const float4 sh = ((const float4*)shift)[tid];
    float4 o;
    o.x = tf32r(sh.x + sc.x * (v.x - mean) * inv);
    o.y = tf32r(sh.y + sc.y * (v.y - mean) * inv);
    o.z = tf32r(sh.z + sc.z * (v.z - mean) * inv);
    o.w = tf32r(sh.w + sc.w * (v.w - mean) * inv);
    ((float4*)(out + (size_t)row * D_))[tid] = o;
}

// ---------------- TF32 mma.sync NT GEMM: C[M,N] = A[M,K] . B[N,K]^T --------
#define BM 128
#define BN 128
#define BK 32
#define PADS 36
#define STAGEF (BM*PADS + BN*PADS)
#define NSTAGE 3
#define GEMM_SMEM (NSTAGE*STAGEF*4)

__device__ __forceinline__ void stage_load(uint32_t smbase, int s,
                                           const float* __restrict__ Ab,
                                           const float* __restrict__ Bb,
                                           int K, int k0, int tid) {
    const uint32_t abase = smbase + (uint32_t)s * STAGEF * 4;
    const uint32_t bbase = abase + BM * PADS * 4;
    #pragma unroll
    for (int i = 0; i < 4; i++) {
        int idx = i * 256 + tid;
        int r = idx >> 3, g = idx & 7;
        cp16(abase + (r * PADS + g * 4) * 4, Ab + (size_t)r * K + k0 + g * 4);
        cp16(bbase + (r * PADS + g * 4) * 4, Bb + (size_t)r * K + k0 + g * 4);
    }
}

template<bool BIAS, bool GELU_ACT, bool RES, bool ROUND>
__global__ __launch_bounds__(256, 1) void gemm_mma(
    const float* __restrict__ A, const float* __restrict__ B,
    const float* __restrict__ bias, const float* __restrict__ res,
    float* __restrict__ C, int M, int N, int K)
{
    extern __shared__ float smf[];
    const uint32_t smbase = smem_u32(smf);
    const int tid  = threadIdx.x;
    const int wid  = tid >> 5, lane = tid & 31;
    const int wm   = wid >> 2, wn = wid & 3;
    const int g    = lane >> 2, t = lane & 3;

    const float* Ab = A + (size_t)blockIdx.y * BM * K;
    const float* Bb = B + (size_t)blockIdx.x * BN * K;

    float acc[4][4][4];
    #pragma unroll
    for (int i = 0; i < 4; i++)
        #pragma unroll
        for (int j = 0; j < 4; j++)
            #pragma unroll
            for (int q = 0; q < 4; q++) acc[i][j][q] = 0.f;

    const int nch = K >> 5;

    stage_load(smbase, 0, Ab, Bb, K, 0, tid);
    asm volatile("cp.async.commit_group;" ::: "memory");
    stage_load(smbase, 1, Ab, Bb, K, BK, tid);
    asm volatile("cp.async.commit_group;" ::: "memory");

    for (int i = 0; i < nch; i++) {
        const int s = i % NSTAGE;
        if (i + 2 < nch) {
            asm volatile("cp.async.wait_group 1;" ::: "memory");
        } else {
            asm volatile("cp.async.wait_group 0;" ::: "memory");
        }
        __syncthreads();
        if (i + 2 < nch) {
            stage_load(smbase, (i + 2) % NSTAGE, Ab, Bb, K, (i + 2) * BK, tid);
            asm volatile("cp.async.commit_group;" ::: "memory");
        }

        const float* as = smf + (size_t)s * STAGEF;
        const float* bs = as + BM * PADS;

        #pragma unroll
        for (int ks = 0; ks < 4; ks++) {
            const int k0 = ks * 8;
            uint32_t af[4][4], bf[4][2];
            #pragma unroll
            for (int mt = 0; mt < 4; mt++) {
                const int row = wm * 64 + mt * 16;
                af[mt][0] = __float_as_uint(as[(row + g)     * PADS + k0 + t]);
                af[mt][1] = __float_as_uint(as[(row + g + 8) * PADS + k0 + t]);
                af[mt][2] = __float_as_uint(as[(row + g)     * PADS + k0 + t + 4]);
                af[mt][3] = __float_as_uint(as[(row + g + 8) * PADS + k0 + t + 4]);
            }
            #pragma unroll
            for (int nt = 0; nt < 4; nt++) {
                const int col = wn * 32 + nt * 8 + g;
                bf[nt][0] = __float_as_uint(bs[col * PADS + k0 + t]);
                bf[nt][1] = __float_as_uint(bs[col * PADS + k0 + t + 4]);
            }
            #pragma unroll
            for (int mt = 0; mt < 4; mt++)
                #pragma unroll
                for (int nt = 0; nt < 4; nt++)
                    mma_tf32(acc[mt][nt][0], acc[mt][nt][1], acc[mt][nt][2], acc[mt][nt][3],
                             af[mt][0], af[mt][1], af[mt][2], af[mt][3],
                             bf[nt][0], bf[nt][1]);
        }
        __syncthreads();
    }

    #pragma unroll
    for (int mt = 0; mt < 4; mt++) {
        const int r0 = blockIdx.y * BM + wm * 64 + mt * 16 + g;
        #pragma unroll
        for (int nt = 0; nt < 4; nt++) {
            const int c0 = blockIdx.x * BN + wn * 32 + nt * 8 + 2 * t;
            float b0 = 0.f, b1 = 0.f;
            if (BIAS) { b0 = bias[c0]; b1 = bias[c0 + 1]; }
            float v00 = acc[mt][nt][0] + b0, v01 = acc[mt][nt][1] + b1;
            float v10 = acc[mt][nt][2] + b0, v11 = acc[mt][nt][3] + b1;
            if (GELU_ACT) { v00 = gelu_f(v00); v01 = gelu_f(v01);
                            v10 = gelu_f(v10); v11 = gelu_f(v11); }
            if (RES) {
                const float2 r0v = *(const float2*)(res + (size_t)r0 * N + c0);
                const float2 r1v = *(const float2*)(res + (size_t)(r0 + 8) * N + c0);
                v00 += r0v.x; v01 += r0v.y; v10 += r1v.x; v11 += r1v.y;
            }
            if (ROUND) { v00 = tf32r(v00); v01 = tf32r(v01);
                         v10 = tf32r(v10); v11 = tf32r(v11); }
            *(float2*)(C + (size_t)r0 * N + c0)       = make_float2(v00, v01);
            *(float2*)(C + (size_t)(r0 + 8) * N + c0) = make_float2(v10, v11);
        }
    }
}

// ---------------- Tensor-core causal flash attention (tf32, HD=64) ---------
// QT=128 (8 warps x m16), KT=64. Double-buffered cp.async K/V tiles.
// Per warp: S(16x64) via mma -> softmax (fexp, FMA pipe) -> P to smem -> O += P.V
#define AQT 128
#define AKT 64
#define KPAD 68
#define VPAD 72
#define PPAD 68
#define ATTN_SMEM ((2*(AKT*KPAD + AKT*VPAD) + AQT*PPAD) * 4)

__global__ __launch_bounds__(256) void attn_tc(
    const float* __restrict__ qkv, float* __restrict__ ctx)
{
    extern __shared__ float sm[];
    float* kb[2]; float* vb[2];
    kb[0] = sm;
    vb[0] = kb[0] + AKT * KPAD;
    kb[1] = vb[0] + AKT * VPAD;
    vb[1] = kb[1] + AKT * KPAD;
    float* ps = vb[1] + AKT * VPAD;      // P region; also Q staging

    const int qt  = (int)gridDim.x - 1 - (int)blockIdx.x;  // heavy blocks first
    const int bh  = blockIdx.y;
    const int b   = bh >> 4;
    const int h   = bh & 15;
    const int tid = threadIdx.x;
    const int w   = tid >> 5, lane = tid & 31;
    const int g   = lane >> 2, t = lane & 3;
    const int mrow = w * 16;
    const int tok0 = b * S_ + qt * AQT;

    // ---- stage Q (scaled by 1/8) into ps, then extract A-fragments ----
    for (int i = tid; i < AQT * 16; i += 256) {
        const int r = i >> 4, c = i & 15;
        float4 v = *((const float4*)(qkv + (size_t)(tok0 + r) * (3 * D_) + h * HD_) + c);
        v.x *= 0.125f; v.y *= 0.125f; v.z *= 0.125f; v.w *= 0.125f;
        *(float4*)(ps + r * PPAD + c * 4) = v;
    }
    __syncthreads();
    uint32_t qf[8][4];
    #pragma unroll
    for (int kc = 0; kc < 8; kc++) {
        const int k0 = kc * 8;
        qf[kc][0] = __float_as_uint(ps[(mrow + g)     * PPAD + k0 + t]);
        qf[kc][1] = __float_as_uint(ps[(mrow + g + 8) * PPAD + k0 + t]);
        qf[kc][2] = __float_as_uint(ps[(mrow + g)     * PPAD + k0 + t + 4]);
        qf[kc][3] = __float_as_uint(ps[(mrow + g + 8) * PPAD + k0 + t + 4]);
    }

    float o[8][4];
    #pragma unroll
    for (int nt = 0; nt < 8; nt++)
        #pragma unroll
        for (int q = 0; q < 4; q++) o[nt][q] = 0.f;
    float m0 = -1e30f, m1 = -1e30f, l0 = 0.f, l1 = 0.f;

    const int ntiles = 2 * qt + 2;
    const int qrow0 = qt * AQT + mrow + g;
    const int qrow1 = qrow0 + 8;

    // prologue: load tile 0
    {
        const uint32_t ka = smem_u32(kb[0]), va = smem_u32(vb[0]);
        for (int i = tid; i < AKT * 16; i += 256) {
            const int r = i >> 4, c = i & 15;
            const size_t base = (size_t)(b * S_ + r) * (3 * D_) + h * HD_ + c * 4;
            cp16(ka + (r * KPAD + c * 4) * 4, qkv + base + D_);
            cp16(va + (r * VPAD + c * 4) * 4, qkv + base + 2 * D_);
        }
        asm volatile("cp.async.commit_group;" ::: "memory");
    }

    for (int j = 0; j < ntiles; j++) {
        __syncthreads();   // everyone done reading buffer (j+1)&1 from iter j-1
        if (j + 1 < ntiles) {
            const int nb = (j + 1) & 1;
            const uint32_t ka = smem_u32(kb[nb]), va = smem_u32(vb[nb]);
            for (int i = tid; i < AKT * 16; i += 256) {
                const int r = i >> 4, c = i & 15;
                const size_t base = (size_t)(b * S_ + (j + 1) * AKT + r) * (3 * D_) + h * HD_ + c * 4;
                cp16(ka + (r * KPAD + c * 4) * 4, qkv + base + D_);
                cp16(va + (r * VPAD + c * 4) * 4, qkv + base + 2 * D_);
            }
            asm volatile("cp.async.commit_group;" ::: "memory");
            asm volatile("cp.async.wait_group 1;" ::: "memory");
        } else {
            asm volatile("cp.async.wait_group 0;" ::: "memory");
        }
        __syncthreads();

        const float* ks = kb[j & 1];
        const float* vs = vb[j & 1];
        const int k0abs = j * AKT;

        // ---- S = Q . K^T ----
        float sa[8][4];
        #pragma unroll
        for (int nt = 0; nt < 8; nt++)
            #pragma unroll
            for (int q = 0; q < 4; q++) sa[nt][q] = 0.f;
        #pragma unroll
        for (int kc = 0; kc < 8; kc++) {
            const int k0 = kc * 8;
            #pragma unroll
            for (int nt = 0; nt < 8; nt++) {
                const uint32_t b0 = __float_as_uint(ks[(nt * 8 + g) * KPAD + k0 + t]);
                const uint32_t b1 = __float_as_uint(ks[(nt * 8 + g) * KPAD + k0 + t + 4]);
                mma_tf32(sa[nt][0], sa[nt][1], sa[nt][2], sa[nt][3],
                         qf[kc][0], qf[kc][1], qf[kc][2], qf[kc][3], b0, b1);
            }
        }

        // ---- causal mask (only last two tiles of this block) ----
        if (j >= 2 * qt) {
            #pragma unroll
            for (int nt = 0; nt < 8; nt++) {
                const int col = k0abs + nt * 8 + 2 * t;
                if (col     > qrow0) sa[nt][0] = -1e30f;
                if (col + 1 > qrow0) sa[nt][1] = -1e30f;
                if (col     > qrow1) sa[nt][2] = -1e30f;
                if (col + 1 > qrow1) sa[nt][3] = -1e30f;
            }
        }

        // ---- online softmax ----
        float r0 = -1e30f, r1 = -1e30f;
        #pragma unroll
        for (int nt = 0; nt < 8; nt++) {
            r0 = fmaxf(r0, fmaxf(sa[nt][0], sa[nt][1]));
            r1 = fmaxf(r1, fmaxf(sa[nt][2], sa[nt][3]));
        }
        r0 = fmaxf(r0, __shfl_xor_sync(0xffffffffu, r0, 1));
        r0 = fmaxf(r0, __shfl_xor_sync(0xffffffffu, r0, 2));
        r1 = fmaxf(r1, __shfl_xor_sync(0xffffffffu, r1, 1));
        r1 = fmaxf(r1, __shfl_xor_sync(0xffffffffu, r1, 2));
        const float mn0 = fmaxf(m0, r0), mn1 = fmaxf(m1, r1);
        const float cr0 = fexp(m0 - mn0), cr1 = fexp(m1 - mn1);
        m0 = mn0; m1 = mn1;

        float p0 = 0.f, p1 = 0.f;
        __syncwarp();
        #pragma unroll
        for (int nt = 0; nt < 8; nt++) {
            const float e0 = fexp(sa[nt][0] - mn0);
            const float e1 = fexp(sa[nt][1] - mn0);
            const float e2 = fexp(sa[nt][2] - mn1);
            const float e3 = fexp(sa[nt][3] - mn1);
            p0 += e0 + e1; p1 += e2 + e3;
            *(float2*)(ps + (mrow + g)     * PPAD + nt * 8 + 2 * t) = make_float2(tf32r(e0), tf32r(e1));
            *(float2*)(ps + (mrow + g + 8) * PPAD + nt * 8 + 2 * t) = make_float2(tf32r(e2), tf32r(e3));
        }
        p0 += __shfl_xor_sync(0xffffffffu, p0, 1);
        p0 += __shfl_xor_sync(0xffffffffu, p0, 2);
        p1 += __shfl_xor_sync(0xffffffffu, p1, 1);
        p1 += __shfl_xor_sync(0xffffffffu, p1, 2);
        l0 = l0 * cr0 + p0;
        l1 = l1 * cr1 + p1;

        #pragma unroll
        for (int nt = 0; nt < 8; nt++) {
            o[nt][0] *= cr0; o[nt][1] *= cr0;
            o[nt][2] *= cr1; o[nt][3] *= cr1;
        }
        __syncwarp();

        // ---- O += P . V ----
        #pragma unroll
        for (int kc = 0; kc < 8; kc++) {
            const int k0 = kc * 8;
            uint32_t a0 = __float_as_uint(ps[(mrow + g)     * PPAD + k0 + t]);
            uint32_t a1 = __float_as_uint(ps[(mrow + g + 8) * PPAD + k0 + t]);
            uint32_t a2 = __float_as_uint(ps[(mrow + g)     * PPAD + k0 + t + 4]);
            uint32_t a3 = __float_as_uint(ps[(mrow + g + 8) * PPAD + k0 + t + 4]);
            #pragma unroll
            for (int nt = 0; nt < 8; nt++) {
                const uint32_t b0 = __float_as_uint(vs[(k0 + t)     * VPAD + nt * 8 + g]);
                const uint32_t b1 = __float_as_uint(vs[(k0 + t + 4) * VPAD + nt * 8 + g]);
                mma_tf32(o[nt][0], o[nt][1], o[nt][2], o[nt][3], a0, a1, a2, a3, b0, b1);
            }
        }
    }

    const float il0 = 1.0f / l0, il1 = 1.0f / l1;
    const int row0 = tok0 + mrow + g;
    #pragma unroll
    for (int nt = 0; nt < 8; nt++) {
        const int col = h * HD_ + nt * 8 + 2 * t;
        *(float2*)(ctx + (size_t)row0 * D_ + col) =
            make_float2(tf32r(o[nt][0] * il0), tf32r(o[nt][1] * il0));
        *(float2*)(ctx + (size_t)(row0 + 8) * D_ + col) =
            make_float2(tf32r(o[nt][2] * il1), tf32r(o[nt][3] * il1));
    }
}

// ---------------- launch ---------------------------------------------------
extern "C" void kernel_launch(void* const* d_in, const int* in_sizes, int n_in,
                              void* d_out, int out_size)
{
    const float* x      = (const float*)d_in[0];
    const float* scale1 = (const float*)d_in[1];
    const float* shift1 = (const float*)d_in[2];
    const float* Wqkv   = (const float*)d_in[3];
    const float* Wo_w   = (const float*)d_in[4];
    const float* Wo_b   = (const float*)d_in[5];
    const float* scale2 = (const float*)d_in[6];
    const float* shift2 = (const float*)d_in[7];
    const float* W1     = (const float*)d_in[8];
    const float* b1     = (const float*)d_in[9];
    const float* W2     = (const float*)d_in[10];
    const float* b2     = (const float*)d_in[11];
    float* out = (float*)d_out;

    float *h, *qkv, *ctx, *x1, *h2, *mbuf, *wqkv, *wo, *w1, *w2;
    cudaGetSymbolAddress((void**)&h,    g_h);
    cudaGetSymbolAddress((void**)&qkv,  g_qkv);
    cudaGetSymbolAddress((void**)&ctx,  g_ctx);
    cudaGetSymbolAddress((void**)&x1,   g_x1);
    cudaGetSymbolAddress((void**)&h2,   g_h2);
    cudaGetSymbolAddress((void**)&mbuf, g_m);
    cudaGetSymbolAddress((void**)&wqkv, g_wqkv);
    cudaGetSymbolAddress((void**)&wo,   g_wo);
    cudaGetSymbolAddress((void**)&w1,   g_w1);
    cudaGetSymbolAddress((void**)&w2,   g_w2);

    cudaFuncSetAttribute(attn_tc, cudaFuncAttributeMaxDynamicSharedMemorySize, ATTN_SMEM);
    cudaFuncSetAttribute(gemm_mma<false,false,false,true>, cudaFuncAttributeMaxDynamicSharedMemorySize, GEMM_SMEM);
    cudaFuncSetAttribute(gemm_mma<true,false,true,false>,  cudaFuncAttributeMaxDynamicSharedMemorySize, GEMM_SMEM);
    cudaFuncSetAttribute(gemm_mma<true,true,false,true>,   cudaFuncAttributeMaxDynamicSharedMemorySize, GEMM_SMEM);

    // 0. round weights to tf32 (RNA) into scratch
    round_w_kernel<<<(3*D_*D_/4 + 255)/256, 256>>>(Wqkv, wqkv, 3*D_*D_/4);
    round_w_kernel<<<(D_*D_/4   + 255)/256, 256>>>(Wo_w, wo,   D_*D_/4);
    round_w_kernel<<<(FF_*D_/4  + 255)/256, 256>>>(W1,   w1,   FF_*D_/4);
    round_w_kernel<<<(D_*FF_/4  + 255)/256, 256>>>(W2,   w2,   D_*FF_/4);

    // 1. LN1 (tf32-rounded output)
    ln_kernel<<<T_, 256>>>(x, scale1, shift1, h);
    // 2. QKV = h @ Wqkv^T, tf32-rounded output  [4096,3072,1024]
    gemm_mma<false,false,false,true><<<dim3(3*D_/BN, T_/BM), 256, GEMM_SMEM>>>(
        h, wqkv, nullptr, nullptr, qkv, T_, 3*D_, D_);
    // 3. tensor-core causal attention (ctx tf32-rounded)
    attn_tc<<<dim3(S_/AQT, B_*H_), 256, ATTN_SMEM>>>(qkv, ctx);
    // 4. x1 = x + ctx @ Wo^T + Wo_b   [4096,1024,1024]
    gemm_mma<true,false,true,false><<<dim3(D_/BN, T_/BM), 256, GEMM_SMEM>>>(
        ctx, wo, Wo_b, x, x1, T_, D_, D_);
    // 5. LN2 (tf32-rounded output)
    ln_kernel<<<T_, 256>>>(x1, scale2, shift2, h2);
    // 6. m = gelu(h2 @ W1^T + b1), tf32-rounded   [4096,4096,1024]
    gemm_mma<true,true,false,true><<<dim3(FF_/BN, T_/BM), 256, GEMM_SMEM>>>(
        h2, w1, b1, nullptr, mbuf, T_, FF_, D_);
    // 7. out = x1 + m @ W2^T + b2   [4096,1024,4096]
    gemm_mma<true,false,true,false><<<dim3(D_/BN, T_/BM), 256, GEMM_SMEM>>>(
        mbuf, w2, b2, x1, out, T_, D_, FF_);
}

// round 5
// speedup vs baseline: 3.3556x; 1.0901x over previous
#include <cuda_runtime.h>
#include <math.h>
#include <stdint.h>

#define D_     1024
#define H_     16
#define HD_    64
#define FF_    4096
#define B_     2
#define S_     2048
#define T_     (B_*S_)     // 4096 tokens
#define EPS_   1e-5f

// ---------------- scratch (device globals; allocation-free) ----------------
__device__ float g_h  [T_ * D_];        // LN1 out (tf32-rounded)
__device__ float g_qkv[T_ * 3 * D_];    // qkv (tf32-rounded)
__device__ float g_ctx[T_ * D_];        // attention context (tf32-rounded)
__device__ float g_x1 [T_ * D_];        // x + attn proj (exact)
__device__ float g_h2 [T_ * D_];        // LN2 out (tf32-rounded)
__device__ float g_m  [T_ * FF_];       // MLP hidden (tf32-rounded)
// tf32-rounded weights
__device__ float g_wqkv[3 * D_ * D_];
__device__ float g_wo  [D_ * D_];
__device__ float g_w1  [FF_ * D_];
__device__ float g_w2  [D_ * FF_];

// ---------------- small helpers -------------------------------------------
__device__ __forceinline__ uint32_t smem_u32(const void* p) {
    uint32_t a;
    asm("{ .reg .u64 t; cvta.to.shared.u64 t, %1; cvt.u32.u64 %0, t; }" : "=r"(a) : "l"(p));
    return a;
}
__device__ __forceinline__ float tf32r(float x) {
    uint32_t u;
    asm("cvt.rna.tf32.f32 %0, %1;" : "=r"(u) : "f"(x));
    return __uint_as_float(u);
}
__device__ __forceinline__ float gelu_f(float x) {
    const float c = 0.7978845608028654f;
    float x3 = x * x * x;
    return 0.5f * x * (1.0f + tanhf(c * (x + 0.044715f * x3)));
}
__device__ __forceinline__ void cp16(uint32_t dst, const void* src) {
    asm volatile("cp.async.cg.shared.global [%0], [%1], 16;" :: "r"(dst), "l"(src) : "memory");
}
__device__ __forceinline__ void mma_tf32(float& c0, float& c1, float& c2, float& c3,
                                         uint32_t a0, uint32_t a1, uint32_t a2, uint32_t a3,
                                         uint32_t b0, uint32_t b1) {
    asm volatile(
        "mma.sync.aligned.m16n8k8.row.col.f32.tf32.tf32.f32 "
        "{%0,%1,%2,%3}, {%4,%5,%6,%7}, {%8,%9}, {%0,%1,%2,%3};"
        : "+f"(c0), "+f"(c1), "+f"(c2), "+f"(c3)
        : "r"(a0), "r"(a1), "r"(a2), "r"(a3), "r"(b0), "r"(b1));
}
// fast exp on the FMA pipe (no MUFU)
__device__ __forceinline__ float fexp(float x) {
    float y = fmaxf(x * 1.4426950408889634f, -126.0f);
    float z = y + 12582912.0f;
    float n = z - 12582912.0f;
    float f = y - n;
    float q = f * 0.6931471805599453f;
    float p = 0.008333345f;
    p = p * q + 0.041666667f;
    p = p * q + 0.166666667f;
    p = p * q + 0.5f;
    p = p * q + 1.0f;
    p = p * q + 1.0f;
    int e = (int)n;
    return __int_as_float(__float_as_int(p) + (e << 23));
}

// ---------------- tf32 rounding pass for weights ---------------------------
__global__ __launch_bounds__(256) void round_w_kernel(const float* __restrict__ in,
                                                      float* __restrict__ out, int n4) {
    int i = blockIdx.x * 256 + threadIdx.x;
    if (i < n4) {
        float4 v = ((const float4*)in)[i];
        v.x = tf32r(v.x); v.y = tf32r(v.y); v.z = tf32r(v.z); v.w = tf32r(v.w);
        ((float4*)out)[i] = v;
    }
}

// ---------------- LayerNorm (ddof=1, eps added to std), tf32-rounded out ---
__global__ __launch_bounds__(256) void ln_kernel(
    const float* __restrict__ x, const float* __restrict__ scale,
    const float* __restrict__ shift, float* __restrict__ out)
{
    const int row = blockIdx.x;
    const int tid = threadIdx.x;
    const float4 v = ((const float4*)(x + (size_t)row * D_))[tid];

    float s  = v.x + v.y + v.z + v.w;
    float ss = v.x*v.x + v.y*v.y + v.z*v.z + v.w*v.w;
    #pragma unroll
    for (int o = 16; o > 0; o >>= 1) {
        s  += __shfl_xor_sync(0xffffffffu, s,  o);
        ss += __shfl_xor_sync(0xffffffffu, ss, o);
    }
    __shared__ float sm[8], sm2[8];
    const int w = tid >> 5, l = tid & 31;
    if (l == 0) { sm[w] = s; sm2[w] = ss; }
    __syncthreads();
    float ts = 0.f, tss = 0.f;
    #pragma unroll
    for (int i = 0; i < 8; i++) { ts += sm[i]; tss += sm2[i]; }

    const float mean = ts * (1.0f / D_);
    const float var  = (tss - (float)D_ * mean * mean) * (1.0f / (D_ - 1));
    const float inv  = 1.0f / (sqrtf(var) + EPS_);

    const float4 sc = ((const float4*)scale)[tid];
    const float4 sh = ((const float4*)shift)[tid];
    float4 o;
    o.x = tf32r(sh.x + sc.x * (v.x - mean) * inv);
    o.y = tf32r(sh.y + sc.y * (v.y - mean) * inv);
    o.z = tf32r(sh.z + sc.z * (v.z - mean) * inv);
    o.w = tf32r(sh.w + sc.w * (v.w - mean) * inv);
    ((float4*)(out + (size_t)row * D_))[tid] = o;
}

// ---------------- TF32 mma.sync NT GEMM: C[M,N] = A[M,K] . B[N,K]^T --------
// CTA 128x256, BK=32, 8 warps (2x2 grid of 64x64 warp tiles), 3-stage cp.async.
#define BM 128
#define BN 256
#define BK 32
#define PADS 36
#define ASTR (BM*PADS)                 // 4608 floats
#define BSTR (BN*PADS)                 // 9216 floats
#define STAGEF (ASTR + BSTR)           // 13824 floats / stage
#define NSTAGE 3
#define GEMM_SMEM (NSTAGE*STAGEF*4)    // 165888 B

__device__ __forceinline__ void stage_load(uint32_t smbase, int s,
                                           const float* __restrict__ Ab,
                                           const float* __restrict__ Bb,
                                           int K, int k0, int tid) {
    const uint32_t abase = smbase + (uint32_t)s * STAGEF * 4;
    const uint32_t bbase = abase + ASTR * 4;
    #pragma unroll
    for (int i = 0; i < 4; i++) {                 // A: 1024 granules
        int idx = i * 256 + tid;
        int r = idx >> 3, g = idx & 7;
        cp16(abase + (r * PADS + g * 4) * 4, Ab + (size_t)r * K + k0 + g * 4);
    }
    #pragma unroll
    for (int i = 0; i < 8; i++) {                 // B: 2048 granules
        int idx = i * 256 + tid;
        int r = idx >> 3, g = idx & 7;
        cp16(bbase + (r * PADS + g * 4) * 4, Bb + (size_t)r * K + k0 + g * 4);
    }
}

template<bool BIAS, bool GELU_ACT, bool RES, bool ROUND>
__global__ __launch_bounds__(256, 1) void gemm_mma(
    const float* __restrict__ A, const float* __restrict__ B,
    const float* __restrict__ bias, const float* __restrict__ res,
    float* __restrict__ C, int M, int N, int K)
{
    extern __shared__ float smf[];
    const uint32_t smbase = smem_u32(smf);
    const int tid  = threadIdx.x;
    const int wid  = tid >> 5, lane = tid & 31;
    const int wm   = wid >> 2, wn = wid & 3;       // 2 x 4 warp grid, tiles 64x64
    const int g    = lane >> 2, t = lane & 3;

    const float* Ab = A + (size_t)blockIdx.y * BM * K;
    const float* Bb = B + (size_t)blockIdx.x * BN * K;

    float acc[4][8][4];
    #pragma unroll
    for (int i = 0; i < 4; i++)
        #pragma unroll
        for (int j = 0; j < 8; j++)
            #pragma unroll
            for (int q = 0; q < 4; q++) acc[i][j][q] = 0.f;

    const int nch = K >> 5;

    stage_load(smbase, 0, Ab, Bb, K, 0, tid);
    asm volatile("cp.async.commit_group;" ::: "memory");
    stage_load(smbase, 1, Ab, Bb, K, BK, tid);
    asm volatile("cp.async.commit_group;" ::: "memory");

    for (int i = 0; i < nch; i++) {
        const int s = i % NSTAGE;
        if (i + 2 < nch) {
            asm volatile("cp.async.wait_group 1;" ::: "memory");
        } else {
            asm volatile("cp.async.wait_group 0;" ::: "memory");
        }
        __syncthreads();
        if (i + 2 < nch) {
            stage_load(smbase, (i + 2) % NSTAGE, Ab, Bb, K, (i + 2) * BK, tid);
            asm volatile("cp.async.commit_group;" ::: "memory");
        }

        const float* as = smf + (size_t)s * STAGEF;
        const float* bs = as + ASTR;

        #pragma unroll
        for (int ks = 0; ks < 4; ks++) {
            const int k0 = ks * 8;
            uint32_t af[4][4], bf[8][2];
            #pragma unroll
            for (int mt = 0; mt < 4; mt++) {
                const int row = wm * 64 + mt * 16;
                af[mt][0] = __float_as_uint(as[(row + g)     * PADS + k0 + t]);
                af[mt][1] = __float_as_uint(as[(row + g + 8) * PADS + k0 + t]);
                af[mt][2] = __float_as_uint(as[(row + g)     * PADS + k0 + t + 4]);
                af[mt][3] = __float_as_uint(as[(row + g + 8) * PADS + k0 + t + 4]);
            }
            #pragma unroll
            for (int nt = 0; nt < 8; nt++) {
                const int col = wn * 64 + nt * 8 + g;
                bf[nt][0] = __float_as_uint(bs[col * PADS + k0 + t]);
                bf[nt][1] = __float_as_uint(bs[col * PADS + k0 + t + 4]);
            }
            #pragma unroll
            for (int mt = 0; mt < 4; mt++)
                #pragma unroll
                for (int nt = 0; nt < 8; nt++)
                    mma_tf32(acc[mt][nt][0], acc[mt][nt][1], acc[mt][nt][2], acc[mt][nt][3],
                             af[mt][0], af[mt][1], af[mt][2], af[mt][3],
                             bf[nt][0], bf[nt][1]);
        }
        __syncthreads();
    }

    // ------------- epilogue -------------
    #pragma unroll
    for (int mt = 0; mt < 4; mt++) {
        const int r0 = blockIdx.y * BM + wm * 64 + mt * 16 + g;
        #pragma unroll
        for (int nt = 0; nt < 8; nt++) {
            const int c0 = blockIdx.x * BN + wn * 64 + nt * 8 + 2 * t;
            float b0 = 0.f, b1 = 0.f;
            if (BIAS) { b0 = bias[c0]; b1 = bias[c0 + 1]; }
            float v00 = acc[mt][nt][0] + b0, v01 = acc[mt][nt][1] + b1;
            float v10 = acc[mt][nt][2] + b0, v11 = acc[mt][nt][3] + b1;
            if (GELU_ACT) { v00 = gelu_f(v00); v01 = gelu_f(v01);
                            v10 = gelu_f(v10); v11 = gelu_f(v11); }
            if (RES) {
                const float2 r0v = *(const float2*)(res + (size_t)r0 * N + c0);
                const float2 r1v = *(const float2*)(res + (size_t)(r0 + 8) * N + c0);
                v00 += r0v.x; v01 += r0v.y; v10 += r1v.x; v11 += r1v.y;
            }
            if (ROUND) { v00 = tf32r(v00); v01 = tf32r(v01);
                         v10 = tf32r(v10); v11 = tf32r(v11); }
            *(float2*)(C + (size_t)r0 * N + c0)       = make_float2(v00, v01);
            *(float2*)(C + (size_t)(r0 + 8) * N + c0) = make_float2(v10, v11);
        }
    }
}

// ---------------- Tensor-core causal flash attention (tf32, HD=64) ---------
#define AQT 128
#define AKT 64
#define KPAD 68
#define VPAD 72
#define PPAD 68
#define ATTN_SMEM ((2*(AKT*KPAD + AKT*VPAD) + AQT*PPAD) * 4)

__global__ __launch_bounds__(256) void attn_tc(
    const float* __restrict__ qkv, float* __restrict__ ctx)
{
    extern __shared__ float sm[];
    float* kb[2]; float* vb[2];
    kb[0] = sm;
    vb[0] = kb[0] + AKT * KPAD;
    kb[1] = vb[0] + AKT * VPAD;
    vb[1] = kb[1] + AKT * KPAD;
    float* ps = vb[1] + AKT * VPAD;

    const int qt  = (int)gridDim.x - 1 - (int)blockIdx.x;
    const int bh  = blockIdx.y;
    const int b   = bh >> 4;
    const int h   = bh & 15;
    const int tid = threadIdx.x;
    const int w   = tid >> 5, lane = tid & 31;
    const int g   = lane >> 2, t = lane & 3;
    const int mrow = w * 16;
    const int tok0 = b * S_ + qt * AQT;

    for (int i = tid; i < AQT * 16; i += 256) {
        const int r = i >> 4, c = i & 15;
        float4 v = *((const float4*)(qkv + (size_t)(tok0 + r) * (3 * D_) + h * HD_) + c);
        v.x *= 0.125f; v.y *= 0.125f; v.z *= 0.125f; v.w *= 0.125f;
        *(float4*)(ps + r * PPAD + c * 4) = v;
    }
    __syncthreads();
    uint32_t qf[8][4];
    #pragma unroll
    for (int kc = 0; kc < 8; kc++) {
        const int k0 = kc * 8;
        qf[kc][0] = __float_as_uint(ps[(mrow + g)     * PPAD + k0 + t]);
        qf[kc][1] = __float_as_uint(ps[(mrow + g + 8) * PPAD + k0 + t]);
        qf[kc][2] = __float_as_uint(ps[(mrow + g)     * PPAD + k0 + t + 4]);
        qf[kc][3] = __float_as_uint(ps[(mrow + g + 8) * PPAD + k0 + t + 4]);
    }

    float o[8][4];
    #pragma unroll
    for (int nt = 0; nt < 8; nt++)
        #pragma unroll
        for (int q = 0; q < 4; q++) o[nt][q] = 0.f;
    float m0 = -1e30f, m1 = -1e30f, l0 = 0.f, l1 = 0.f;

    const int ntiles = 2 * qt + 2;
    const int qrow0 = qt * AQT + mrow + g;
    const int qrow1 = qrow0 + 8;

    {
        const uint32_t ka = smem_u32(kb[0]), va = smem_u32(vb[0]);
        for (int i = tid; i < AKT * 16; i += 256) {
            const int r = i >> 4, c = i & 15;
            const size_t base = (size_t)(b * S_ + r) * (3 * D_) + h * HD_ + c * 4;
            cp16(ka + (r * KPAD + c * 4) * 4, qkv + base + D_);
            cp16(va + (r * VPAD + c * 4) * 4, qkv + base + 2 * D_);
        }
        asm volatile("cp.async.commit_group;" ::: "memory");
    }

    for (int j = 0; j < ntiles; j++) {
        __syncthreads();
        if (j + 1 < ntiles) {
            const int nb = (j + 1) & 1;
            const uint32_t ka = smem_u32(kb[nb]), va = smem_u32(vb[nb]);
            for (int i = tid; i < AKT * 16; i += 256) {
                const int r = i >> 4, c = i & 15;
                const size_t base = (size_t)(b * S_ + (j + 1) * AKT + r) * (3 * D_) + h * HD_ + c * 4;
                cp16(ka + (r * KPAD + c * 4) * 4, qkv + base + D_);
                cp16(va + (r * VPAD + c * 4) * 4, qkv + base + 2 * D_);
            }
            asm volatile("cp.async.commit_group;" ::: "memory");
            asm volatile("cp.async.wait_group 1;" ::: "memory");
        } else {
            asm volatile("cp.async.wait_group 0;" ::: "memory");
        }
        __syncthreads();

        const float* ks = kb[j & 1];
        const float* vs = vb[j & 1];
        const int k0abs = j * AKT;

        float sa[8][4];
        #pragma unroll
        for (int nt = 0; nt < 8; nt++)
            #pragma unroll
            for (int q = 0; q < 4; q++) sa[nt][q] = 0.f;
        #pragma unroll
        for (int kc = 0; kc < 8; kc++) {
            const int k0 = kc * 8;
            #pragma unroll
            for (int nt = 0; nt < 8; nt++) {
                const uint32_t b0 = __float_as_uint(ks[(nt * 8 + g) * KPAD + k0 + t]);
                const uint32_t b1 = __float_as_uint(ks[(nt * 8 + g) * KPAD + k0 + t + 4]);
                mma_tf32(sa[nt][0], sa[nt][1], sa[nt][2], sa[nt][3],
                         qf[kc][0], qf[kc][1], qf[kc][2], qf[kc][3], b0, b1);
            }
        }

        if (j >= 2 * qt) {
            #pragma unroll
            for (int nt = 0; nt < 8; nt++) {
                const int col = k0abs + nt * 8 + 2 * t;
                if (col     > qrow0) sa[nt][0] = -1e30f;
                if (col + 1 > qrow0) sa[nt][1] = -1e30f;
                if (col     > qrow1) sa[nt][2] = -1e30f;
                if (col + 1 > qrow1) sa[nt][3] = -1e30f;
            }
        }

        float r0 = -1e30f, r1 = -1e30f;
        #pragma unroll
        for (int nt = 0; nt < 8; nt++) {
            r0 = fmaxf(r0, fmaxf(sa[nt][0], sa[nt][1]));
            r1 = fmaxf(r1, fmaxf(sa[nt][2], sa[nt][3]));
        }
        r0 = fmaxf(r0, __shfl_xor_sync(0xffffffffu, r0, 1));
        r0 = fmaxf(r0, __shfl_xor_sync(0xffffffffu, r0, 2));
        r1 = fmaxf(r1, __shfl_xor_sync(0xffffffffu, r1, 1));
        r1 = fmaxf(r1, __shfl_xor_sync(0xffffffffu, r1, 2));
        const float mn0 = fmaxf(m0, r0), mn1 = fmaxf(m1, r1);
        const float cr0 = fexp(m0 - mn0), cr1 = fexp(m1 - mn1);
        m0 = mn0; m1 = mn1;

        float p0 = 0.f, p1 = 0.f;
        __syncwarp();
        #pragma unroll
        for (int nt = 0; nt < 8; nt++) {
            const float e0 = fexp(sa[nt][0] - mn0);
            const float e1 = fexp(sa[nt][1] - mn0);
            const float e2 = fexp(sa[nt][2] - mn1);
            const float e3 = fexp(sa[nt][3] - mn1);
            p0 += e0 + e1; p1 += e2 + e3;
            *(float2*)(ps + (mrow + g)     * PPAD + nt * 8 + 2 * t) = make_float2(tf32r(e0), tf32r(e1));
            *(float2*)(ps + (mrow + g + 8) * PPAD + nt * 8 + 2 * t) = make_float2(tf32r(e2), tf32r(e3));
        }
        p0 += __shfl_xor_sync(0xffffffffu, p0, 1);
        p0 += __shfl_xor_sync(0xffffffffu, p0, 2);
        p1 += __shfl_xor_sync(0xffffffffu, p1, 1);
        p1 += __shfl_xor_sync(0xffffffffu, p1, 2);
        l0 = l0 * cr0 + p0;
        l1 = l1 * cr1 + p1;

        #pragma unroll
        for (int nt = 0; nt < 8; nt++) {
            o[nt][0] *= cr0; o[nt][1] *= cr0;
            o[nt][2] *= cr1; o[nt][3] *= cr1;
        }
        __syncwarp();

        #pragma unroll
        for (int kc = 0; kc < 8; kc++) {
            const int k0 = kc * 8;
            uint32_t a0 = __float_as_uint(ps[(mrow + g)     * PPAD + k0 + t]);
            uint32_t a1 = __float_as_uint(ps[(mrow + g + 8) * PPAD + k0 + t]);
            uint32_t a2 = __float_as_uint(ps[(mrow + g)     * PPAD + k0 + t + 4]);
            uint32_t a3 = __float_as_uint(ps[(mrow + g + 8) * PPAD + k0 + t + 4]);
            #pragma unroll
            for (int nt = 0; nt < 8; nt++) {
                const uint32_t b0 = __float_as_uint(vs[(k0 + t)     * VPAD + nt * 8 + g]);
                const uint32_t b1 = __float_as_uint(vs[(k0 + t + 4) * VPAD + nt * 8 + g]);
                mma_tf32(o[nt][0], o[nt][1], o[nt][2], o[nt][3], a0, a1, a2, a3, b0, b1);
            }
        }
    }

    const float il0 = 1.0f / l0, il1 = 1.0f / l1;
    const int row0 = tok0 + mrow + g;
    #pragma unroll
    for (int nt = 0; nt < 8; nt++) {
        const int col = h * HD_ + nt * 8 + 2 * t;
        *(float2*)(ctx + (size_t)row0 * D_ + col) =
            make_float2(tf32r(o[nt][0] * il0), tf32r(o[nt][1] * il0));
        *(float2*)(ctx + (size_t)(row0 + 8) * D_ + col) =
            make_float2(tf32r(o[nt][2] * il1), tf32r(o[nt][3] * il1));
    }
}

// ---------------- launch ---------------------------------------------------
extern "C" void kernel_launch(void* const* d_in, const int* in_sizes, int n_in,
                              void* d_out, int out_size)
{
    const float* x      = (const float*)d_in[0];
    const float* scale1 = (const float*)d_in[1];
    const float* shift1 = (const float*)d_in[2];
    const float* Wqkv   = (const float*)d_in[3];
    const float* Wo_w   = (const float*)d_in[4];
    const float* Wo_b   = (const float*)d_in[5];
    const float* scale2 = (const float*)d_in[6];
    const float* shift2 = (const float*)d_in[7];
    const float* W1     = (const float*)d_in[8];
    const float* b1     = (const float*)d_in[9];
    const float* W2     = (const float*)d_in[10];
    const float* b2     = (const float*)d_in[11];
    float* out = (float*)d_out;

    float *h, *qkv, *ctx, *x1, *h2, *mbuf, *wqkv, *wo, *w1, *w2;
    cudaGetSymbolAddress((void**)&h,    g_h);
    cudaGetSymbolAddress((void**)&qkv,  g_qkv);
    cudaGetSymbolAddress((void**)&ctx,  g_ctx);
    cudaGetSymbolAddress((void**)&x1,   g_x1);
    cudaGetSymbolAddress((void**)&h2,   g_h2);
    cudaGetSymbolAddress((void**)&mbuf, g_m);
    cudaGetSymbolAddress((void**)&wqkv, g_wqkv);
    cudaGetSymbolAddress((void**)&wo,   g_wo);
    cudaGetSymbolAddress((void**)&w1,   g_w1);
    cudaGetSymbolAddress((void**)&w2,   g_w2);

    cudaFuncSetAttribute(attn_tc, cudaFuncAttributeMaxDynamicSharedMemorySize, ATTN_SMEM);
    cudaFuncSetAttribute(gemm_mma<false,false,false,true>, cudaFuncAttributeMaxDynamicSharedMemorySize, GEMM_SMEM);
    cudaFuncSetAttribute(gemm_mma<true,false,true,false>,  cudaFuncAttributeMaxDynamicSharedMemorySize, GEMM_SMEM);
    cudaFuncSetAttribute(gemm_mma<true,true,false,true>,   cudaFuncAttributeMaxDynamicSharedMemorySize, GEMM_SMEM);

    // 0. round weights to tf32 (RNA) into scratch
    round_w_kernel<<<(3*D_*D_/4 + 255)/256, 256>>>(Wqkv, wqkv, 3*D_*D_/4);
    round_w_kernel<<<(D_*D_/4   + 255)/256, 256>>>(Wo_w, wo,   D_*D_/4);
    round_w_kernel<<<(FF_*D_/4  + 255)/256, 256>>>(W1,   w1,   FF_*D_/4);
    round_w_kernel<<<(D_*FF_/4  + 255)/256, 256>>>(W2,   w2,   D_*FF_/4);

    // 1. LN1 (tf32-rounded output)
    ln_kernel<<<T_, 256>>>(x, scale1, shift1, h);
    // 2. QKV = h @ Wqkv^T, tf32-rounded output  [4096,3072,1024]
    gemm_mma<false,false,false,true><<<dim3(3*D_/BN, T_/BM), 256, GEMM_SMEM>>>(
        h, wqkv, nullptr, nullptr, qkv, T_, 3*D_, D_);
    // 3. tensor-core causal attention (ctx tf32-rounded)
    attn_tc<<<dim3(S_/AQT, B_*H_), 256, ATTN_SMEM>>>(qkv, ctx);
    // 4. x1 = x + ctx @ Wo^T + Wo_b   [4096,1024,1024]
    gemm_mma<true,false,true,false><<<dim3(D_/BN, T_/BM), 256, GEMM_SMEM>>>(
        ctx, wo, Wo_b, x, x1, T_, D_, D_);
    // 5. LN2 (tf32-rounded output)
    ln_kernel<<<T_, 256>>>(x1, scale2, shift2, h2);
    // 6. m = gelu(h2 @ W1^T + b1), tf32-rounded   [4096,4096,1024]
    gemm_mma<true,true,false,true><<<dim3(FF_/BN, T_/BM), 256, GEMM_SMEM>>>(
        h2, w1, b1, nullptr, mbuf, T_, FF_, D_);
    // 7. out = x1 + m @ W2^T + b2   [4096,1024,4096]
    gemm_mma<true,false,true,false><<<dim3(D_/BN, T_/BM), 256, GEMM_SMEM>>>(
        mbuf, w2, b2, x1, out, T_, D_, FF_);
}

// round 6
// speedup vs baseline: 3.3893x; 1.0100x over previous
#include <cuda_runtime.h>
#include <math.h>
#include <stdint.h>

#define D_     1024
#define H_     16
#define HD_    64
#define FF_    4096
#define B_     2
#define S_     2048
#define T_     (B_*S_)     // 4096 tokens
#define EPS_   1e-5f

// ---------------- scratch (device globals; allocation-free) ----------------
__device__ float g_h  [T_ * D_];
__device__ float g_qkv[T_ * 3 * D_];
__device__ float g_ctx[T_ * D_];
__device__ float g_x1 [T_ * D_];
__device__ float g_h2 [T_ * D_];
__device__ float g_m  [T_ * FF_];
__device__ float g_wqkv[3 * D_ * D_];
__device__ float g_wo  [D_ * D_];
__device__ float g_w1  [FF_ * D_];
__device__ float g_w2  [D_ * FF_];

// ---------------- small helpers -------------------------------------------
__device__ __forceinline__ uint32_t smem_u32(const void* p) {
    uint32_t a;
    asm("{ .reg .u64 t; cvta.to.shared.u64 t, %1; cvt.u32.u64 %0, t; }" : "=r"(a) : "l"(p));
    return a;
}
__device__ __forceinline__ float tf32r(float x) {
    uint32_t u;
    asm("cvt.rna.tf32.f32 %0, %1;" : "=r"(u) : "f"(x));
    return __uint_as_float(u);
}
__device__ __forceinline__ float gelu_f(float x) {
    const float c = 0.7978845608028654f;
    float x3 = x * x * x;
    return 0.5f * x * (1.0f + tanhf(c * (x + 0.044715f * x3)));
}
__device__ __forceinline__ void cp16(uint32_t dst, const void* src) {
    asm volatile("cp.async.cg.shared.global [%0], [%1], 16;" :: "r"(dst), "l"(src) : "memory");
}
__device__ __forceinline__ void mma_tf32(float& c0, float& c1, float& c2, float& c3,
                                         uint32_t a0, uint32_t a1, uint32_t a2, uint32_t a3,
                                         uint32_t b0, uint32_t b1) {
    asm volatile(
        "mma.sync.aligned.m16n8k8.row.col.f32.tf32.tf32.f32 "
        "{%0,%1,%2,%3}, {%4,%5,%6,%7}, {%8,%9}, {%0,%1,%2,%3};"
        : "+f"(c0), "+f"(c1), "+f"(c2), "+f"(c3)
        : "r"(a0), "r"(a1), "r"(a2), "r"(a3), "r"(b0), "r"(b1));
}
__device__ __forceinline__ float fexp(float x) {
    float y = fmaxf(x * 1.4426950408889634f, -126.0f);
    float z = y + 12582912.0f;
    float n = z - 12582912.0f;
    float f = y - n;
    float q = f * 0.6931471805599453f;
    float p = 0.008333345f;
    p = p * q + 0.041666667f;
    p = p * q + 0.166666667f;
    p = p * q + 0.5f;
    p = p * q + 1.0f;
    p = p * q + 1.0f;
    int e = (int)n;
    return __int_as_float(__float_as_int(p) + (e << 23));
}

// ---------------- tf32 rounding pass for weights ---------------------------
__global__ __launch_bounds__(256) void round_w_kernel(const float* __restrict__ in,
                                                      float* __restrict__ out, int n4) {
    int i = blockIdx.x * 256 + threadIdx.x;
    if (i < n4) {
        float4 v = ((const float4*)in)[i];
        v.x = tf32r(v.x); v.y = tf32r(v.y); v.z = tf32r(v.z); v.w = tf32r(v.w);
        ((float4*)out)[i] = v;
    }
}

// ---------------- LayerNorm (ddof=1, eps added to std), tf32-rounded out ---
__global__ __launch_bounds__(256) void ln_kernel(
    const float* __restrict__ x, const float* __restrict__ scale,
    const float* __restrict__ shift, float* __restrict__ out)
{
    const int row = blockIdx.x;
    const int tid = threadIdx.x;
    const float4 v = ((const float4*)(x + (size_t)row * D_))[tid];

    float s  = v.x + v.y + v.z + v.w;
    float ss = v.x*v.x + v.y*v.y + v.z*v.z + v.w*v.w;
    #pragma unroll
    for (int o = 16; o > 0; o >>= 1) {
        s  += __shfl_xor_sync(0xffffffffu, s,  o);
        ss += __shfl_xor_sync(0xffffffffu, ss, o);
    }
    __shared__ float sm[8], sm2[8];
    const int w = tid >> 5, l = tid & 31;
    if (l == 0) { sm[w] = s; sm2[w] = ss; }
    __syncthreads();
    float ts = 0.f, tss = 0.f;
    #pragma unroll
    for (int i = 0; i < 8; i++) { ts += sm[i]; tss += sm2[i]; }

    const float mean = ts * (1.0f / D_);
    const float var  = (tss - (float)D_ * mean * mean) * (1.0f / (D_ - 1));
    const float inv  = 1.0f / (sqrtf(var) + EPS_);

    const float4 sc = ((const float4*)scale)[tid];
    const float4 sh = ((const float4*)shift)[tid];
    float4 o;
    o.x = tf32r(sh.x + sc.x * (v.x - mean) * inv);
    o.y = tf32r(sh.y + sc.y * (v.y - mean) * inv);
    o.z = tf32r(sh.z + sc.z * (v.z - mean) * inv);
    o.w = tf32r(sh.w + sc.w * (v.w - mean) * inv);
    ((float4*)(out + (size_t)row * D_))[tid] = o;
}

// ---------------- TF32 mma.sync NT GEMM: C[M,N] = A[M,K] . B[N,K]^T --------
// CTA 128x256, BK=32, 8 warps (2x4 grid of 64x64 tiles), 3-stage cp.async,
// register double-buffered fragments, one barrier per chunk.
#define BM 128
#define BN 256
#define BK 32
#define PADS 36
#define ASTR (BM*PADS)
#define BSTR (BN*PADS)
#define STAGEF (ASTR + BSTR)
#define NSTAGE 3
#define GEMM_SMEM (NSTAGE*STAGEF*4)

__device__ __forceinline__ void stage_load(uint32_t smbase, int s,
                                           const float* __restrict__ Ab,
                                           const float* __restrict__ Bb,
                                           int K, int k0, int tid) {
    const uint32_t abase = smbase + (uint32_t)s * STAGEF * 4;
    const uint32_t bbase = abase + ASTR * 4;
    #pragma unroll
    for (int i = 0; i < 4; i++) {
        int idx = i * 256 + tid;
        int r = idx >> 3, g = idx & 7;
        cp16(abase + (r * PADS + g * 4) * 4, Ab + (size_t)r * K + k0 + g * 4);
    }
    #pragma unroll
    for (int i = 0; i < 8; i++) {
        int idx = i * 256 + tid;
        int r = idx >> 3, g = idx & 7;
        cp16(bbase + (r * PADS + g * 4) * 4, Bb + (size_t)r * K + k0 + g * 4);
    }
}

template<bool BIAS, bool GELU_ACT, bool RES, bool ROUND>
__global__ __launch_bounds__(256, 1) void gemm_mma(
    const float* __restrict__ A, const float* __restrict__ B,
    const float* __restrict__ bias, const float* __restrict__ res,
    float* __restrict__ C, int M, int N, int K)
{
    extern __shared__ float smf[];
    const uint32_t smbase = smem_u32(smf);
    const int tid  = threadIdx.x;
    const int wid  = tid >> 5, lane = tid & 31;
    const int wm   = wid >> 2, wn = wid & 3;
    const int g    = lane >> 2, t = lane & 3;

    const float* Ab = A + (size_t)blockIdx.y * BM * K;
    const float* Bb = B + (size_t)blockIdx.x * BN * K;

    float acc[4][8][4];
    #pragma unroll
    for (int i = 0; i < 4; i++)
        #pragma unroll
        for (int j = 0; j < 8; j++)
            #pragma unroll
            for (int q = 0; q < 4; q++) acc[i][j][q] = 0.f;

    const int nch = K >> 5;

    stage_load(smbase, 0, Ab, Bb, K, 0, tid);
    asm volatile("cp.async.commit_group;" ::: "memory");
    stage_load(smbase, 1, Ab, Bb, K, BK, tid);
    asm volatile("cp.async.commit_group;" ::: "memory");

    // per-thread fragment smem offsets (element indices)
    const int arow = wm * 64 + g;
    const int bcol = wn * 64 + g;

    for (int i = 0; i < nch; i++) {
        const int s = i % NSTAGE;
        if (i + 2 < nch) {
            asm volatile("cp.async.wait_group 1;" ::: "memory");
        } else {
            asm volatile("cp.async.wait_group 0;" ::: "memory");
        }
        __syncthreads();
        if (i + 2 < nch) {
            stage_load(smbase, (i + 2) % NSTAGE, Ab, Bb, K, (i + 2) * BK, tid);
            asm volatile("cp.async.commit_group;" ::: "memory");
        }

        const float* as = smf + (size_t)s * STAGEF;
        const float* bs = as + ASTR;

        uint32_t af[2][4][4], bf[2][8][2];

        // prefetch k-slice 0 fragments
        #pragma unroll
        for (int mt = 0; mt < 4; mt++) {
            const int row = arow + mt * 16;
            af[0][mt][0] = __float_as_uint(as[row       * PADS + t]);
            af[0][mt][1] = __float_as_uint(as[(row + 8) * PADS + t]);
            af[0][mt][2] = __float_as_uint(as[row       * PADS + t + 4]);
            af[0][mt][3] = __float_as_uint(as[(row + 8) * PADS + t + 4]);
        }
        #pragma unroll
        for (int nt = 0; nt < 8; nt++) {
            const int col = bcol + nt * 8;
            bf[0][nt][0] = __float_as_uint(bs[col * PADS + t]);
            bf[0][nt][1] = __float_as_uint(bs[col * PADS + t + 4]);
        }

        #pragma unroll
        for (int ks = 0; ks < 4; ks++) {
            const int cur = ks & 1, nxt = cur ^ 1;
            if (ks < 3) {
                const int k0 = (ks + 1) * 8;
                #pragma unroll
                for (int mt = 0; mt < 4; mt++) {
                    const int row = arow + mt * 16;
                    af[nxt][mt][0] = __float_as_uint(as[row       * PADS + k0 + t]);
                    af[nxt][mt][1] = __float_as_uint(as[(row + 8) * PADS + k0 + t]);
                    af[nxt][mt][2] = __float_as_uint(as[row       * PADS + k0 + t + 4]);
                    af[nxt][mt][3] = __float_as_uint(as[(row + 8) * PADS + k0 + t + 4]);
                }
                #pragma unroll
                for (int nt = 0; nt < 8; nt++) {
                    const int col = bcol + nt * 8;
                    bf[nxt][nt][0] = __float_as_uint(bs[col * PADS + k0 + t]);
                    bf[nxt][nt][1] = __float_as_uint(bs[col * PADS + k0 + t + 4]);
                }
            }
            #pragma unroll
            for (int mt = 0; mt < 4; mt++)
                #pragma unroll
                for (int nt = 0; nt < 8; nt++)
                    mma_tf32(acc[mt][nt][0], acc[mt][nt][1], acc[mt][nt][2], acc[mt][nt][3],
                             af[cur][mt][0], af[cur][mt][1], af[cur][mt][2], af[cur][mt][3],
                             bf[cur][nt][0], bf[cur][nt][1]);
        }
        // no trailing barrier: loop-top sync protects stage reuse
    }

    // ------------- epilogue -------------
    #pragma unroll
    for (int mt = 0; mt < 4; mt++) {
        const int r0 = blockIdx.y * BM + wm * 64 + mt * 16 + g;
        #pragma unroll
        for (int nt = 0; nt < 8; nt++) {
            const int c0 = blockIdx.x * BN + wn * 64 + nt * 8 + 2 * t;
            float b0 = 0.f, b1 = 0.f;
            if (BIAS) { b0 = bias[c0]; b1 = bias[c0 + 1]; }
            float v00 = acc[mt][nt][0] + b0, v01 = acc[mt][nt][1] + b1;
            float v10 = acc[mt][nt][2] + b0, v11 = acc[mt][nt][3] + b1;
            if (GELU_ACT) { v00 = gelu_f(v00); v01 = gelu_f(v01);
                            v10 = gelu_f(v10); v11 = gelu_f(v11); }
            if (RES) {
                const float2 r0v = *(const float2*)(res + (size_t)r0 * N + c0);
                const float2 r1v = *(const float2*)(res + (size_t)(r0 + 8) * N + c0);
                v00 += r0v.x; v01 += r0v.y; v10 += r1v.x; v11 += r1v.y;
            }
            if (ROUND) { v00 = tf32r(v00); v01 = tf32r(v01);
                         v10 = tf32r(v10); v11 = tf32r(v11); }
            *(float2*)(C + (size_t)r0 * N + c0)       = make_float2(v00, v01);
            *(float2*)(C + (size_t)(r0 + 8) * N + c0) = make_float2(v10, v11);
        }
    }
}

// ---------------- Tensor-core causal flash attention (tf32, HD=64) ---------
#define AQT 128
#define AKT 64
#define KPAD 68
#define VPAD 72
#define PPAD 68
#define ATTN_SMEM ((2*(AKT*KPAD + AKT*VPAD) + AQT*PPAD) * 4)

__global__ __launch_bounds__(256) void attn_tc(
    const float* __restrict__ qkv, float* __restrict__ ctx)
{
    extern __shared__ float sm[];
    float* kb[2]; float* vb[2];
    kb[0] = sm;
    vb[0] = kb[0] + AKT * KPAD;
    kb[1] = vb[0] + AKT * VPAD;
    vb[1] = kb[1] + AKT * KPAD;
    float* ps = vb[1] + AKT * VPAD;

    const int qt  = (int)gridDim.x - 1 - (int)blockIdx.x;
    const int bh  = blockIdx.y;
    const int b   = bh >> 4;
    const int h   = bh & 15;
    const int tid = threadIdx.x;
    const int w   = tid >> 5, lane = tid & 31;
    const int g   = lane >> 2, t = lane & 3;
    const int mrow = w * 16;
    const int tok0 = b * S_ + qt * AQT;

    for (int i = tid; i < AQT * 16; i += 256) {
        const int r = i >> 4, c = i & 15;
        float4 v = *((const float4*)(qkv + (size_t)(tok0 + r) * (3 * D_) + h * HD_) + c);
        v.x *= 0.125f; v.y *= 0.125f; v.z *= 0.125f; v.w *= 0.125f;
        *(float4*)(ps + r * PPAD + c * 4) = v;
    }
    __syncthreads();
    uint32_t qf[8][4];
    #pragma unroll
    for (int kc = 0; kc < 8; kc++) {
        const int k0 = kc * 8;
        qf[kc][0] = __float_as_uint(ps[(mrow + g)     * PPAD + k0 + t]);
        qf[kc][1] = __float_as_uint(ps[(mrow + g + 8) * PPAD + k0 + t]);
        qf[kc][2] = __float_as_uint(ps[(mrow + g)     * PPAD + k0 + t + 4]);
        qf[kc][3] = __float_as_uint(ps[(mrow + g + 8) * PPAD + k0 + t + 4]);
    }

    float o[8][4];
    #pragma unroll
    for (int nt = 0; nt < 8; nt++)
        #pragma unroll
        for (int q = 0; q < 4; q++) o[nt][q] = 0.f;
    float m0 = -1e30f, m1 = -1e30f, l0 = 0.f, l1 = 0.f;

    const int ntiles = 2 * qt + 2;
    const int qrow0 = qt * AQT + mrow + g;
    const int qrow1 = qrow0 + 8;

    {
        const uint32_t ka = smem_u32(kb[0]), va = smem_u32(vb[0]);
        for (int i = tid; i < AKT * 16; i += 256) {
            const int r = i >> 4, c = i & 15;
            const size_t base = (size_t)(b * S_ + r) * (3 * D_) + h * HD_ + c * 4;
            cp16(ka + (r * KPAD + c * 4) * 4, qkv + base + D_);
            cp16(va + (r * VPAD + c * 4) * 4, qkv + base + 2 * D_);
        }
        asm volatile("cp.async.commit_group;" ::: "memory");
    }

    for (int j = 0; j < ntiles; j++) {
        __syncthreads();
        if (j + 1 < ntiles) {
            const int nb = (j + 1) & 1;
            const uint32_t ka = smem_u32(kb[nb]), va = smem_u32(vb[nb]);
            for (int i = tid; i < AKT * 16; i += 256) {
                const int r = i >> 4, c = i & 15;
                const size_t base = (size_t)(b * S_ + (j + 1) * AKT + r) * (3 * D_) + h * HD_ + c * 4;
                cp16(ka + (r * KPAD + c * 4) * 4, qkv + base + D_);
                cp16(va + (r * VPAD + c * 4) * 4, qkv + base + 2 * D_);
            }
            asm volatile("cp.async.commit_group;" ::: "memory");
            asm volatile("cp.async.wait_group 1;" ::: "memory");
        } else {
            asm volatile("cp.async.wait_group 0;" ::: "memory");
        }
        __syncthreads();

        const float* ks = kb[j & 1];
        const float* vs = vb[j & 1];
        const int k0abs = j * AKT;

        float sa[8][4];
        #pragma unroll
        for (int nt = 0; nt < 8; nt++)
            #pragma unroll
            for (int q = 0; q < 4; q++) sa[nt][q] = 0.f;
        #pragma unroll
        for (int kc = 0; kc < 8; kc++) {
            const int k0 = kc * 8;
            #pragma unroll
            for (int nt = 0; nt < 8; nt++) {
                const uint32_t b0 = __float_as_uint(ks[(nt * 8 + g) * KPAD + k0 + t]);
                const uint32_t b1 = __float_as_uint(ks[(nt * 8 + g) * KPAD + k0 + t + 4]);
                mma_tf32(sa[nt][0], sa[nt][1], sa[nt][2], sa[nt][3],
                         qf[kc][0], qf[kc][1], qf[kc][2], qf[kc][3], b0, b1);
            }
        }

        if (j >= 2 * qt) {
            #pragma unroll
            for (int nt = 0; nt < 8; nt++) {
                const int col = k0abs + nt * 8 + 2 * t;
                if (col     > qrow0) sa[nt][0] = -1e30f;
                if (col + 1 > qrow0) sa[nt][1] = -1e30f;
                if (col     > qrow1) sa[nt][2] = -1e30f;
                if (col + 1 > qrow1) sa[nt][3] = -1e30f;
            }
        }

        float r0 = -1e30f, r1 = -1e30f;
        #pragma unroll
        for (int nt = 0; nt < 8; nt++) {
            r0 = fmaxf(r0, fmaxf(sa[nt][0], sa[nt][1]));
            r1 = fmaxf(r1, fmaxf(sa[nt][2], sa[nt][3]));
        }
        r0 = fmaxf(r0, __shfl_xor_sync(0xffffffffu, r0, 1));
        r0 = fmaxf(r0, __shfl_xor_sync(0xffffffffu, r0, 2));
        r1 = fmaxf(r1, __shfl_xor_sync(0xffffffffu, r1, 1));
        r1 = fmaxf(r1, __shfl_xor_sync(0xffffffffu, r1, 2));
        const float mn0 = fmaxf(m0, r0), mn1 = fmaxf(m1, r1);
        const float cr0 = fexp(m0 - mn0), cr1 = fexp(m1 - mn1);
        m0 = mn0; m1 = mn1;

        float p0 = 0.f, p1 = 0.f;
        __syncwarp();
        #pragma unroll
        for (int nt = 0; nt < 8; nt++) {
            const float e0 = fexp(sa[nt][0] - mn0);
            const float e1 = fexp(sa[nt][1] - mn0);
            const float e2 = fexp(sa[nt][2] - mn1);
            const float e3 = fexp(sa[nt][3] - mn1);
            p0 += e0 + e1; p1 += e2 + e3;
            *(float2*)(ps + (mrow + g)     * PPAD + nt * 8 + 2 * t) = make_float2(tf32r(e0), tf32r(e1));
            *(float2*)(ps + (mrow + g + 8) * PPAD + nt * 8 + 2 * t) = make_float2(tf32r(e2), tf32r(e3));
        }
        p0 += __shfl_xor_sync(0xffffffffu, p0, 1);
        p0 += __shfl_xor_sync(0xffffffffu, p0, 2);
        p1 += __shfl_xor_sync(0xffffffffu, p1, 1);
        p1 += __shfl_xor_sync(0xffffffffu, p1, 2);
        l0 = l0 * cr0 + p0;
        l1 = l1 * cr1 + p1;

        #pragma unroll
        for (int nt = 0; nt < 8; nt++) {
            o[nt][0] *= cr0; o[nt][1] *= cr0;
            o[nt][2] *= cr1; o[nt][3] *= cr1;
        }
        __syncwarp();

        #pragma unroll
        for (int kc = 0; kc < 8; kc++) {
            const int k0 = kc * 8;
            uint32_t a0 = __float_as_uint(ps[(mrow + g)     * PPAD + k0 + t]);
            uint32_t a1 = __float_as_uint(ps[(mrow + g + 8) * PPAD + k0 + t]);
            uint32_t a2 = __float_as_uint(ps[(mrow + g)     * PPAD + k0 + t + 4]);
            uint32_t a3 = __float_as_uint(ps[(mrow + g + 8) * PPAD + k0 + t + 4]);
            #pragma unroll
            for (int nt = 0; nt < 8; nt++) {
                const uint32_t b0 = __float_as_uint(vs[(k0 + t)     * VPAD + nt * 8 + g]);
                const uint32_t b1 = __float_as_uint(vs[(k0 + t + 4) * VPAD + nt * 8 + g]);
                mma_tf32(o[nt][0], o[nt][1], o[nt][2], o[nt][3], a0, a1, a2, a3, b0, b1);
            }
        }
    }

    const float il0 = 1.0f / l0, il1 = 1.0f / l1;
    const int row0 = tok0 + mrow + g;
    #pragma unroll
    for (int nt = 0; nt < 8; nt++) {
        const int col = h * HD_ + nt * 8 + 2 * t;
        *(float2*)(ctx + (size_t)row0 * D_ + col) =
            make_float2(tf32r(o[nt][0] * il0), tf32r(o[nt][1] * il0));
        *(float2*)(ctx + (size_t)(row0 + 8) * D_ + col) =
            make_float2(tf32r(o[nt][2] * il1), tf32r(o[nt][3] * il1));
    }
}

// ---------------- launch ---------------------------------------------------
extern "C" void kernel_launch(void* const* d_in, const int* in_sizes, int n_in,
                              void* d_out, int out_size)
{
    const float* x      = (const float*)d_in[0];
    const float* scale1 = (const float*)d_in[1];
    const float* shift1 = (const float*)d_in[2];
    const float* Wqkv   = (const float*)d_in[3];
    const float* Wo_w   = (const float*)d_in[4];
    const float* Wo_b   = (const float*)d_in[5];
    const float* scale2 = (const float*)d_in[6];
    const float* shift2 = (const float*)d_in[7];
    const float* W1     = (const float*)d_in[8];
    const float* b1     = (const float*)d_in[9];
    const float* W2     = (const float*)d_in[10];
    const float* b2     = (const float*)d_in[11];
    float* out = (float*)d_out;

    float *h, *qkv, *ctx, *x1, *h2, *mbuf, *wqkv, *wo, *w1, *w2;
    cudaGetSymbolAddress((void**)&h,    g_h);
    cudaGetSymbolAddress((void**)&qkv,  g_qkv);
    cudaGetSymbolAddress((void**)&ctx,  g_ctx);
    cudaGetSymbolAddress((void**)&x1,   g_x1);
    cudaGetSymbolAddress((void**)&h2,   g_h2);
    cudaGetSymbolAddress((void**)&mbuf, g_m);
    cudaGetSymbolAddress((void**)&wqkv, g_wqkv);
    cudaGetSymbolAddress((void**)&wo,   g_wo);
    cudaGetSymbolAddress((void**)&w1,   g_w1);
    cudaGetSymbolAddress((void**)&w2,   g_w2);

    cudaFuncSetAttribute(attn_tc, cudaFuncAttributeMaxDynamicSharedMemorySize, ATTN_SMEM);
    cudaFuncSetAttribute(gemm_mma<false,false,false,true>, cudaFuncAttributeMaxDynamicSharedMemorySize, GEMM_SMEM);
    cudaFuncSetAttribute(gemm_mma<true,false,true,false>,  cudaFuncAttributeMaxDynamicSharedMemorySize, GEMM_SMEM);
    cudaFuncSetAttribute(gemm_mma<true,true,false,true>,   cudaFuncAttributeMaxDynamicSharedMemorySize, GEMM_SMEM);

    round_w_kernel<<<(3*D_*D_/4 + 255)/256, 256>>>(Wqkv, wqkv, 3*D_*D_/4);
    round_w_kernel<<<(D_*D_/4   + 255)/256, 256>>>(Wo_w, wo,   D_*D_/4);
    round_w_kernel<<<(FF_*D_/4  + 255)/256, 256>>>(W1,   w1,   FF_*D_/4);
    round_w_kernel<<<(D_*FF_/4  + 255)/256, 256>>>(W2,   w2,   D_*FF_/4);

    ln_kernel<<<T_, 256>>>(x, scale1, shift1, h);
    gemm_mma<false,false,false,true><<<dim3(3*D_/BN, T_/BM), 256, GEMM_SMEM>>>(
        h, wqkv, nullptr, nullptr, qkv, T_, 3*D_, D_);
    attn_tc<<<dim3(S_/AQT, B_*H_), 256, ATTN_SMEM>>>(qkv, ctx);
    gemm_mma<true,false,true,false><<<dim3(D_/BN, T_/BM), 256, GEMM_SMEM>>>(
        ctx, wo, Wo_b, x, x1, T_, D_, D_);
    ln_kernel<<<T_, 256>>>(x1, scale2, shift2, h2);
    gemm_mma<true,true,false,true><<<dim3(FF_/BN, T_/BM), 256, GEMM_SMEM>>>(
        h2, w1, b1, nullptr, mbuf, T_, FF_, D_);
    gemm_mma<true,false,true,false><<<dim3(D_/BN, T_/BM), 256, GEMM_SMEM>>>(
        mbuf, w2, b2, x1, out, T_, D_, FF_);
}